// round 14
// baseline (speedup 1.0000x reference)
#include <cuda_runtime.h>
#include <cuda_fp16.h>
#include <math.h>
#include <stdint.h>

#define Bq 2
#define Lq 1536
#define Dq 1024
#define Hq 8
#define Cq 2048
#define DPHq 256
#define Mq (Bq*Lq)   /* 3072 */

typedef __half fp16;

// ---------------- scratch (static device globals; no allocation) ----------------
__device__ __align__(128) fp16  d_xlnf[(size_t)Mq*Dq];
__device__ __align__(128) float d_y[(size_t)Mq*4096];
__device__ __align__(128) fp16  d_x1f[(size_t)Mq*Cq];
__device__ __align__(128) float d_qk[(size_t)Mq*Cq];
__device__ __align__(128) fp16  d_qkf[(size_t)Mq*Cq];
__device__ __align__(128) fp16  d_pjf[(size_t)Mq*4096];
__device__ __align__(128) fp16  d_vbf[(size_t)Mq*Cq];
__device__ __align__(128) fp16  d_xmf[(size_t)Mq*Cq];
__device__ float d_gates[(size_t)Mq*16];
__device__ float d_g[16*Lq];
__device__ float d_M[16*Lq];
__device__ float d_enm[16*Lq];
__device__ __align__(128) fp16  d_w1f[4096*1024];
__device__ __align__(128) fp16  d_cwtf[(size_t)4*Cq*Cq];
__device__ __align__(128) fp16  d_wqkTf[Hq*512*256];
__device__ __align__(128) fp16  d_wvTf[Hq*256*256];
__device__ __align__(128) fp16  d_w2f[1024*2048];

// ---------------- helpers ----------------
__device__ __forceinline__ uint32_t smem_u32(const void* p){
    return (uint32_t)__cvta_generic_to_shared(p);
}
__device__ __forceinline__ void cp16(uint32_t dst, const void* src){
    asm volatile("cp.async.cg.shared.global [%0], [%1], 16;" :: "r"(dst), "l"(src));
}
__device__ __forceinline__ void cp_commit(){ asm volatile("cp.async.commit_group;" ::: "memory"); }
__device__ __forceinline__ void cp_wait0(){ asm volatile("cp.async.wait_group 0;" ::: "memory"); }
__device__ __forceinline__ void cp_wait1(){ asm volatile("cp.async.wait_group 1;" ::: "memory"); }
__device__ __forceinline__ void cp_wait2(){ asm volatile("cp.async.wait_group 2;" ::: "memory"); }

__device__ __forceinline__ void ldsm_x4(uint32_t* r, uint32_t addr){
    asm volatile("ldmatrix.sync.aligned.m8n8.x4.shared.b16 {%0,%1,%2,%3}, [%4];"
                 : "=r"(r[0]), "=r"(r[1]), "=r"(r[2]), "=r"(r[3]) : "r"(addr));
}
__device__ __forceinline__ void ldsm_x4t(uint32_t* r, uint32_t addr){
    asm volatile("ldmatrix.sync.aligned.m8n8.x4.trans.shared.b16 {%0,%1,%2,%3}, [%4];"
                 : "=r"(r[0]), "=r"(r[1]), "=r"(r[2]), "=r"(r[3]) : "r"(addr));
}
__device__ __forceinline__ void mma16816(float* d, const uint32_t* a, const uint32_t* b){
    asm volatile(
        "mma.sync.aligned.m16n8k16.row.col.f32.f16.f16.f32 "
        "{%0,%1,%2,%3}, {%4,%5,%6,%7}, {%8,%9}, {%0,%1,%2,%3};"
        : "+f"(d[0]), "+f"(d[1]), "+f"(d[2]), "+f"(d[3])
        : "r"(a[0]), "r"(a[1]), "r"(a[2]), "r"(a[3]), "r"(b[0]), "r"(b[1]));
}
__device__ __forceinline__ uint32_t pack2(fp16 a, fp16 b){
    uint16_t ua = *(uint16_t*)&a, ub = *(uint16_t*)&b;
    return (uint32_t)ua | ((uint32_t)ub << 16);
}

// ---------------- prep kernels (coalesced) ----------------
__global__ void quant_plain4(const float4* __restrict__ w, __half2* __restrict__ f, long n4){
    long i = (long)blockIdx.x*256 + threadIdx.x;
    if (i >= n4) return;
    float4 v = w[i];
    f[2*i]   = __floats2half2_rn(v.x, v.y);
    f[2*i+1] = __floats2half2_rn(v.z, v.w);
}
__global__ void prep_cwt(const float4* __restrict__ cw, __half2* __restrict__ f2){
    const long NP = (long)Cq*Cq/2;
    long i = (long)blockIdx.x*256 + threadIdx.x;
    if (i >= NP) return;
    float4 a = cw[2*i], b = cw[2*i+1];
    f2[i]        = __floats2half2_rn(a.x, b.x);
    f2[NP + i]   = __floats2half2_rn(a.y, b.y);
    f2[2*NP + i] = __floats2half2_rn(a.z, b.z);
    f2[3*NP + i] = __floats2half2_rn(a.w, b.w);
}
__global__ void prep_wqkv(const float* __restrict__ wqk, const float* __restrict__ wv,
                          fp16* __restrict__ qf, fp16* __restrict__ vf){
    int idx = blockIdx.x*256 + threadIdx.x;
    if (idx < Hq*512*256){
        int hh = idx/(512*256); int r = idx%(512*256); int o = r/256; int i = r%256;
        qf[idx] = __float2half_rn(wqk[hh*131072 + i*512 + o]);
    } else {
        int j = idx - Hq*512*256;
        if (j < Hq*256*256){
            int hh = j/65536; int r = j%65536; int o = r/256; int i = r%256;
            vf[j] = __float2half_rn(wv[hh*65536 + i*256 + o]);
        }
    }
}

// ---------------- LayerNorm on x -> fp16 ----------------
__global__ __launch_bounds__(256) void ln_kernel(const float* __restrict__ x,
        const float* __restrict__ w, const float* __restrict__ bb,
        fp16* __restrict__ of){
    int m = blockIdx.x, t = threadIdx.x;
    __shared__ float s1[256], s2[256];
    float v[4]; float s = 0.f, q = 0.f;
    #pragma unroll
    for (int u=0;u<4;u++){ v[u] = x[(long)m*Dq + t + u*256]; s += v[u]; q += v[u]*v[u]; }
    s1[t] = s; s2[t] = q; __syncthreads();
    for (int off=128; off; off>>=1){
        if (t < off){ s1[t] += s1[t+off]; s2[t] += s2[t+off]; }
        __syncthreads();
    }
    float mu = s1[0]*(1.f/1024.f);
    float var = s2[0]*(1.f/1024.f) - mu*mu;
    float rs = rsqrtf(var + 1e-5f);
    #pragma unroll
    for (int u=0;u<4;u++){
        int c = t + u*256;
        of[(long)m*Dq + c] = __float2half_rn((v[u]-mu)*rs*w[c] + bb[c]);
    }
}

// ---------------- fp16 mma.sync GEMM (512 threads, BK=64): C = A @ B^T ----------------
// epi bits: 1=bias, 2=silu, 4=residual add, 8=conv mode (batch taps + heavy-first y)
struct G5P {
    const fp16 *Af, *Bf;
    float* Cf;
    fp16 *Oh;
    const float* bias; const float* add;
    int K, lda, ldb, ldc, ldo, ldadd, epi, ntaps, ntaps2, splitNmax, cfMin;
    long aZ, bZ, cZ, biasZ, oZ;
    long aTap[2], bTap[2];
    long aTap2[2], bTap2[2];
};

template<int MT>
__global__ __launch_bounds__(512, 1) void hgemm(G5P p){
    constexpr int BM = MT*64;
    constexpr int TA = BM*144;
    constexpr int TB = 128*144;
    constexpr int STG = TA + TB;
    extern __shared__ char sm[];
    int tid = threadIdx.x;
    int warp = tid >> 5, lane = tid & 31;
    int wm = warp >> 2, wn = warp & 3;

    long byy = (p.epi & 8) ? (long)(gridDim.y - 1 - blockIdx.y) : (long)blockIdx.y;
    long m0 = byy*BM;
    int  n0 = blockIdx.x*128;

    long arow; int ntaps; long aT[2], bT[2];
    if (p.epi & 8){
        int batch = (int)(m0 / Lq);
        arow = m0 - (long)batch*Lq;
        if (batch == 0){ ntaps = p.ntaps;  aT[0]=p.aTap[0];  bT[0]=p.bTap[0];  aT[1]=p.aTap[1];  bT[1]=p.bTap[1]; }
        else           { ntaps = p.ntaps2; aT[0]=p.aTap2[0]; bT[0]=p.bTap2[0]; aT[1]=p.aTap2[1]; bT[1]=p.bTap2[1]; }
    } else {
        arow = m0; ntaps = p.ntaps;
        aT[0]=p.aTap[0]; bT[0]=p.bTap[0]; aT[1]=p.aTap[1]; bT[1]=p.bTap[1];
    }

    long aoff = (long)blockIdx.z*p.aZ + arow*p.lda;
    long boff = (long)blockIdx.z*p.bZ + (long)n0*p.ldb;
    int cpt = p.K >> 6;
    int nch = ntaps * cpt;

    uint32_t smb = smem_u32(sm);
    float acc[MT][4][4] = {};

    auto loadChunk = [&](int c){
        int tap = c / cpt;
        int k0  = (c - tap*cpt) << 6;
        uint32_t stg = smb + (c % 3)*STG;
        const fp16* baseA = p.Af + aoff + aT[tap] + k0;
        #pragma unroll
        for (int j = tid; j < BM*8; j += 512){
            int row = j >> 3, ch = j & 7;
            cp16(stg + row*144 + ch*16, baseA + (long)row*p.lda + ch*8);
        }
        const fp16* baseB = p.Bf + boff + bT[tap] + k0;
        #pragma unroll
        for (int j = tid; j < 1024; j += 512){
            int row = j >> 3, ch = j & 7;
            cp16(stg + TA + row*144 + ch*16, baseB + (long)row*p.ldb + ch*8);
        }
    };

    loadChunk(0); cp_commit();
    if (nch > 1){ loadChunk(1); cp_commit(); }

    for (int c=0; c<nch; c++){
        if (c+2 < nch){ loadChunk(c+2); cp_commit(); cp_wait2(); }
        else if (c+1 < nch){ cp_wait1(); }
        else { cp_wait0(); }
        __syncthreads();

        uint32_t stg = smb + (c % 3)*STG;
        uint32_t aB_ = stg, bB = stg + TA;

        int lr = lane & 15, lcs = lane >> 4;
        int gb = lane >> 3, bnr = lane & 7;
        int rowA = wm*(MT*16) + lr;
        int rowB = wn*32 + ((gb >> 1) << 3) + bnr;

        #pragma unroll
        for (int ks=0; ks<4; ks++){
            uint32_t af[MT][4], bf[4][2];
            uint32_t aoffb = (uint32_t)((rowA*9 + ks*2 + lcs) * 16);
            #pragma unroll
            for (int mt=0; mt<MT; mt++)
                ldsm_x4(af[mt], aB_ + aoffb + mt*2304);
            uint32_t boffb = (uint32_t)((rowB*9 + ks*2 + (gb & 1)) * 16);
            uint32_t t4[4];
            #pragma unroll
            for (int np=0; np<2; np++){
                ldsm_x4(t4, bB + boffb + np*2304);
                bf[np*2][0]=t4[0]; bf[np*2][1]=t4[1]; bf[np*2+1][0]=t4[2]; bf[np*2+1][1]=t4[3];
            }
            #pragma unroll
            for (int mt=0; mt<MT; mt++)
                #pragma unroll
                for (int nt=0; nt<4; nt++)
                    mma16816(acc[mt][nt], af[mt], bf[nt]);
        }
        __syncthreads();
    }

    float* eps = (float*)sm;
    #pragma unroll
    for (int mt=0; mt<MT; mt++){
        int r0 = wm*(MT*16) + mt*16 + (lane >> 2);
        #pragma unroll
        for (int nt=0; nt<4; nt++){
            int c0 = wn*32 + nt*8 + (lane & 3)*2;
            eps[r0*132 + c0]       = acc[mt][nt][0];
            eps[r0*132 + c0 + 1]   = acc[mt][nt][1];
            eps[(r0+8)*132 + c0]   = acc[mt][nt][2];
            eps[(r0+8)*132 + c0+1] = acc[mt][nt][3];
        }
    }
    __syncthreads();

    const float* bias = p.bias ? (p.bias + (long)blockIdx.z*p.biasZ) : (const float*)0;
    long czo = (long)blockIdx.z * p.cZ;
    long ozo = (long)blockIdx.z * p.oZ;
    for (int j = tid; j < BM*128; j += 512){
        int rr = j >> 7, cc = j & 127;
        long m = m0 + rr;
        int n = n0 + cc;
        float val = eps[rr*132 + cc];
        if (bias) val += bias[n];
        if (p.epi & 2){ val = val / (1.f + expf(-val)); }
        if (p.epi & 4){ val += p.add[m*p.ldadd + n]; }
        if (p.Cf && n >= p.cfMin) p.Cf[m*p.ldc + czo + n] = val;
        if (n < p.splitNmax)
            p.Oh[m*p.ldo + ozo + n] = __float2half_rn(val);
    }
}

// ---------------- gates (64 rows/block, fp16 smem, low wif traffic) ----------------
__global__ __launch_bounds__(512) void gates_kernel(const fp16* __restrict__ pjf,
        const fp16* __restrict__ vbf, const float* __restrict__ wif,
        const float* __restrict__ bif, float* __restrict__ gates){
    __shared__ fp16 As[64*144];
    __shared__ float Ws[128*17];
    int m0 = blockIdx.x*64;
    int tid = threadIdx.x;
    int r = tid >> 3, gq = tid & 7;
    float acc0 = 0.f, acc1 = 0.f;
    for (int j0=0; j0<6144; j0+=128){
        __syncthreads();
        int hh = j0/768, t0 = j0 - hh*768;
        for (int e = tid; e < 1024; e += 512){
            int row = e >> 4, c = e & 15;
            int t = t0 + c*8;
            long m = m0 + row;
            const fp16* src = (t < 512) ? (pjf + m*4096 + hh*512 + t)
                                        : (vbf + m*2048 + hh*256 + (t-512));
            *(uint4*)(As + row*144 + c*8) = *(const uint4*)src;
        }
        for (int e = tid; e < 2048; e += 512){
            int jj2 = e >> 4, gg = e & 15;
            Ws[jj2*17 + gg] = wif[(long)gg*6144 + j0 + jj2];
        }
        __syncthreads();
        #pragma unroll 4
        for (int j=0;j<128;j++){
            float v = __half2float(As[r*144 + j]);
            acc0 += v*Ws[j*17 + gq*2];
            acc1 += v*Ws[j*17 + gq*2 + 1];
        }
    }
    gates[(long)(m0+r)*16 + gq*2]     = acc0 + bif[gq*2];
    gates[(long)(m0+r)*16 + gq*2 + 1] = acc1 + bif[gq*2 + 1];
}

// ---------------- per-(b,h) scans ----------------
__global__ __launch_bounds__(512) void scan_kernel(const float* __restrict__ gates,
        float* __restrict__ ga, float* __restrict__ Ma, float* __restrict__ ea){
    int bh = blockIdx.x, b = bh >> 3, h = bh & 7;
    int t = threadIdx.x;
    __shared__ float sd[512];
    long base = (long)b*Lq;
    float ls[3], fc[3];
    #pragma unroll
    for (int u=0;u<3;u++){
        int l = t*3 + u;
        float f = gates[(base + l)*16 + 8 + h];
        ls[u] = (f >= 0.f) ? -log1pf(expf(-f)) : (f - log1pf(expf(f)));
    }
    float tot = ls[0] + ls[1] + ls[2];
    sd[t] = tot;
    __syncthreads();
    for (int off=1; off<512; off<<=1){
        float add = (t >= off) ? sd[t-off] : 0.f;
        __syncthreads();
        sd[t] += add;
        __syncthreads();
    }
    float excl = (t > 0) ? sd[t-1] : 0.f;
    fc[0] = excl + ls[0]; fc[1] = fc[0] + ls[1]; fc[2] = fc[1] + ls[2];
    __syncthreads();
    float gv[3], pm[3];
    #pragma unroll
    for (int u=0;u<3;u++){
        int l = t*3 + u;
        float ig = gates[(base + l)*16 + h];
        gv[u] = expf(ig) - fc[u];
    }
    pm[0] = gv[0]; pm[1] = fmaxf(pm[0], gv[1]); pm[2] = fmaxf(pm[1], gv[2]);
    sd[t] = pm[2];
    __syncthreads();
    for (int off=1; off<512; off<<=1){
        float add = (t >= off) ? sd[t-off] : -3.4e38f;
        __syncthreads();
        sd[t] = fmaxf(sd[t], add);
        __syncthreads();
    }
    float exm = (t > 0) ? sd[t-1] : -3.4e38f;
    #pragma unroll
    for (int u=0;u<3;u++){
        int l = t*3 + u;
        float Ml = fmaxf(exm, pm[u]);
        ga[(long)bh*Lq + l] = gv[u];
        Ma[(long)bh*Lq + l] = Ml;
        ea[(long)bh*Lq + l] = expf(-fc[u] - Ml);
    }
}

// ---------------- tensor-core mLSTM attention: 256 threads, 128 q-rows/CTA ----------------
// smem: Q 128x528B | K0 | K1 | V0 | V1 (each 64x528B) | E[64]
#define Q_OFF  0
#define K0_OFF 67584
#define V0_OFF 135168
#define E_OFF  202752
#define ATT_SMEM 203008

__global__ __launch_bounds__(256, 1) void attn2(
    const fp16* __restrict__ pjf, const fp16* __restrict__ vbf,
    const float* __restrict__ qk, const float* __restrict__ y,
    const float* __restrict__ ga, const float* __restrict__ Ma,
    const float* __restrict__ ea, const float* __restrict__ skip,
    const float* __restrict__ hnw,
    fp16* __restrict__ xmf)
{
    extern __shared__ char sm[];
    const uint32_t smb = smem_u32(sm);
    float* Esm = (float*)(sm + E_OFF);

    int tid = threadIdx.x, w = tid >> 5, lane = tid & 31;
    int bh = blockIdx.y, b = bh >> 3, h = bh & 7;
    int jj = (int)gridDim.x - 1 - (int)blockIdx.x;
    long mbase = (long)b*Lq;
    int o0 = jj*128;
    int ntiles = 2*jj + 2;

    int rowg = w*16 + (lane >> 2);
    float F0  = expf(-Ma[(long)bh*Lq + o0 + rowg])     * 0.0625f;
    float F8  = expf(-Ma[(long)bh*Lq + o0 + rowg + 8]) * 0.0625f;
    float en0 = ea[(long)bh*Lq + o0 + rowg];
    float en8 = ea[(long)bh*Lq + o0 + rowg + 8];

    for (int j = tid; j < 4096; j += 256){
        int row = j >> 5, c = j & 31;
        cp16(smb + Q_OFF + row*528 + c*16, pjf + (mbase + o0 + row)*4096 + h*512 + c*8);
    }
    cp_commit();

    auto issueTile = [&](int it){
        long i0 = (long)it*64;
        uint32_t kb = smb + K0_OFF + (it & 1)*33792;
        uint32_t vb2 = smb + V0_OFF + (it & 1)*33792;
        for (int j = tid; j < 2048; j += 256){
            int row = j >> 5, c = j & 31;
            cp16(kb + row*528 + c*16, pjf + (mbase + i0 + row)*4096 + h*512 + 256 + c*8);
        }
        for (int j = tid; j < 2048; j += 256){
            int row = j >> 5, c = j & 31;
            cp16(vb2 + row*528 + c*16, vbf + (mbase + i0 + row)*2048 + h*256 + c*8);
        }
    };
    issueTile(0); cp_commit();
    issueTile(1); cp_commit();

    float accH[32][4];
    #pragma unroll
    for (int g=0; g<32; g++){ accH[g][0]=0.f; accH[g][1]=0.f; accH[g][2]=0.f; accH[g][3]=0.f; }
    uint32_t pk[8][2];
    float rs0 = 0.f, rs1 = 0.f;

    uint32_t qrow = (uint32_t)((w*16 + (lane & 15))*528 + (lane >> 4)*16);
    int gb = lane >> 3;
    uint32_t krow = (uint32_t)(((((gb >> 1) << 3) + (lane & 7)))*528 + (gb & 1)*16);
    uint32_t vrow = (uint32_t)((lane & 15)*528 + (lane >> 4)*16);

    for (int it = 0; it < ntiles; it++){
        cp_wait1();
        if (tid < 64) Esm[tid] = expf(ga[(long)bh*Lq + (long)it*64 + tid]);
        __syncthreads();

        bool active = (it*64 <= o0 + w*16 + 15);
        if (active){
            uint32_t kb = smb + K0_OFF + (it & 1)*33792;
            uint32_t vb2 = smb + V0_OFF + (it & 1)*33792;

            float sacc[8][4];
            #pragma unroll
            for (int g=0; g<8; g++){ sacc[g][0]=0.f; sacc[g][1]=0.f; sacc[g][2]=0.f; sacc[g][3]=0.f; }
            #pragma unroll
            for (int ks=0; ks<16; ks++){
                uint32_t q4[4];
                ldsm_x4(q4, smb + Q_OFF + qrow + ks*32);
                #pragma unroll
                for (int kt=0; kt<4; kt++){
                    uint32_t b4[4];
                    ldsm_x4(b4, kb + krow + kt*(16*528) + ks*32);
                    mma16816(sacc[kt*2],   q4, b4);
                    mma16816(sacc[kt*2+1], q4, b4 + 2);
                }
            }
            bool needmask = (it*64 + 63 > o0 + w*16);
            int qg0 = o0 + rowg, qg8 = qg0 + 8;
            #pragma unroll
            for (int nt=0; nt<8; nt++){
                int cb = nt*8 + (lane & 3)*2;
                int kg = it*64 + cb;
                float e0 = Esm[cb], e1 = Esm[cb+1];
                float w00 = e0*F0, w01 = e1*F0, w10 = e0*F8, w11 = e1*F8;
                if (needmask){
                    if (kg     > qg0) w00 = 0.f;
                    if (kg + 1 > qg0) w01 = 0.f;
                    if (kg     > qg8) w10 = 0.f;
                    if (kg + 1 > qg8) w11 = 0.f;
                }
                float c0 = sacc[nt][0]*w00, c1 = sacc[nt][1]*w01;
                float c2 = sacc[nt][2]*w10, c3 = sacc[nt][3]*w11;
                rs0 += c0 + c1; rs1 += c2 + c3;
                pk[nt][0] = pack2(__float2half_rn(c0), __float2half_rn(c1));
                pk[nt][1] = pack2(__float2half_rn(c2), __float2half_rn(c3));
            }
            #pragma unroll
            for (int kk=0; kk<4; kk++){
                uint32_t aP[4] = { pk[2*kk][0], pk[2*kk][1], pk[2*kk+1][0], pk[2*kk+1][1] };
                #pragma unroll
                for (int dc=0; dc<16; dc++){
                    uint32_t tH[4];
                    ldsm_x4t(tH, vb2 + vrow + kk*(16*528) + dc*32);
                    mma16816(accH[2*dc],   aP, tH);
                    mma16816(accH[2*dc+1], aP, tH + 2);
                }
            }
        }
        __syncthreads();
        if (it + 2 < ntiles) issueTile(it + 2);
        cp_commit();
    }

    rs0 += __shfl_xor_sync(0xffffffffu, rs0, 1);
    rs0 += __shfl_xor_sync(0xffffffffu, rs0, 2);
    rs1 += __shfl_xor_sync(0xffffffffu, rs1, 1);
    rs1 += __shfl_xor_sync(0xffffffffu, rs1, 2);
    float inv0 = 1.f / fmaxf(fabsf(rs0), en0);
    float inv1 = 1.f / fmaxf(fabsf(rs1), en8);

    float s0=0.f, q0=0.f, s1=0.f, q1=0.f;
    #pragma unroll
    for (int g=0; g<32; g++){
        float v0 = accH[g][0]*inv0, v1 = accH[g][1]*inv0;
        float v2 = accH[g][2]*inv1, v3 = accH[g][3]*inv1;
        accH[g][0]=v0; accH[g][1]=v1; accH[g][2]=v2; accH[g][3]=v3;
        s0 += v0 + v1; q0 += v0*v0 + v1*v1;
        s1 += v2 + v3; q1 += v2*v2 + v3*v3;
    }
    s0 += __shfl_xor_sync(0xffffffffu, s0, 1); s0 += __shfl_xor_sync(0xffffffffu, s0, 2);
    q0 += __shfl_xor_sync(0xffffffffu, q0, 1); q0 += __shfl_xor_sync(0xffffffffu, q0, 2);
    s1 += __shfl_xor_sync(0xffffffffu, s1, 1); s1 += __shfl_xor_sync(0xffffffffu, s1, 2);
    q1 += __shfl_xor_sync(0xffffffffu, q1, 1); q1 += __shfl_xor_sync(0xffffffffu, q1, 2);
    float mu0 = s0*(1.f/256.f), var0 = q0*(1.f/256.f) - mu0*mu0, rst0 = rsqrtf(var0 + 1e-5f);
    float mu1 = s1*(1.f/256.f), var1 = q1*(1.f/256.f) - mu1*mu1, rst1 = rsqrtf(var1 + 1e-5f);

    long mr0 = mbase + o0 + rowg;
    long mr8 = mr0 + 8;
    #pragma unroll
    for (int g=0; g<32; g++){
        int d0 = g*8 + (lane & 3)*2;
        int col = h*256 + d0;
        float2 hw = *(const float2*)(hnw + d0);
        float2 sk = *(const float2*)(skip + col);
        {
            float2 q2 = *(const float2*)(qk + mr0*2048 + col);
            float2 x2 = *(const float2*)(y + mr0*4096 + 2048 + col);
            float hv0 = (accH[g][0] - mu0)*rst0*hw.x;
            float hv1 = (accH[g][1] - mu0)*rst0*hw.y;
            float a0 = hv0 + sk.x*q2.x, a1 = hv1 + sk.y*q2.y;
            float r0 = a0 * (x2.x / (1.f + expf(-x2.x)));
            float r1 = a1 * (x2.y / (1.f + expf(-x2.y)));
            *(uint32_t*)(xmf + mr0*2048 + col) = pack2(__float2half_rn(r0), __float2half_rn(r1));
        }
        {
            float2 q2 = *(const float2*)(qk + mr8*2048 + col);
            float2 x2 = *(const float2*)(y + mr8*4096 + 2048 + col);
            float hv0 = (accH[g][2] - mu1)*rst1*hw.x;
            float hv1 = (accH[g][3] - mu1)*rst1*hw.y;
            float a0 = hv0 + sk.x*q2.x, a1 = hv1 + sk.y*q2.y;
            float r0 = a0 * (x2.x / (1.f + expf(-x2.x)));
            float r1 = a1 * (x2.y / (1.f + expf(-x2.y)));
            *(uint32_t*)(xmf + mr8*2048 + col) = pack2(__float2half_rn(r0), __float2half_rn(r1));
        }
    }
}

// ---------------- host ----------------
extern "C" void kernel_launch(void* const* d_in, const int* in_sizes, int n_in,
                              void* d_out, int out_size){
    const float* x      = (const float*)d_in[0];
    const float* ln_w   = (const float*)d_in[1];
    const float* ln_b   = (const float*)d_in[2];
    const float* w1     = (const float*)d_in[3];
    const float* b1     = (const float*)d_in[4];
    const float* conv_w = (const float*)d_in[5];
    const float* conv_b = (const float*)d_in[6];
    const float* skip   = (const float*)d_in[7];
    const float* wqk    = (const float*)d_in[8];
    const float* bqk    = (const float*)d_in[9];
    const float* wv     = (const float*)d_in[10];
    const float* bv     = (const float*)d_in[11];
    const float* wif    = (const float*)d_in[12];
    const float* bif    = (const float*)d_in[13];
    const float* hn_w   = (const float*)d_in[14];
    const float* w2     = (const float*)d_in[15];
    const float* b2     = (const float*)d_in[16];
    float* out = (float*)d_out;

    fp16 *xlnf,*x1f,*qkf,*xmf,*pjf,*vbf;
    fp16 *w1f,*cwtf,*wqkTf,*wvTf,*w2f;
    float *y,*qkb,*gates,*gA,*MA,*eA;
    cudaGetSymbolAddress((void**)&xlnf, d_xlnf);
    cudaGetSymbolAddress((void**)&y,    d_y);
    cudaGetSymbolAddress((void**)&x1f,  d_x1f);
    cudaGetSymbolAddress((void**)&qkb,  d_qk);
    cudaGetSymbolAddress((void**)&qkf,  d_qkf);
    cudaGetSymbolAddress((void**)&pjf,  d_pjf);
    cudaGetSymbolAddress((void**)&vbf,  d_vbf);
    cudaGetSymbolAddress((void**)&xmf,  d_xmf);
    cudaGetSymbolAddress((void**)&gates,d_gates);
    cudaGetSymbolAddress((void**)&gA,   d_g);
    cudaGetSymbolAddress((void**)&MA,   d_M);
    cudaGetSymbolAddress((void**)&eA,   d_enm);
    cudaGetSymbolAddress((void**)&w1f,  d_w1f);
    cudaGetSymbolAddress((void**)&cwtf, d_cwtf);
    cudaGetSymbolAddress((void**)&wqkTf,d_wqkTf);
    cudaGetSymbolAddress((void**)&wvTf, d_wvTf);
    cudaGetSymbolAddress((void**)&w2f,  d_w2f);

    cudaFuncSetAttribute(hgemm<2>, cudaFuncAttributeMaxDynamicSharedMemorySize, 110592);
    cudaFuncSetAttribute(hgemm<1>, cudaFuncAttributeMaxDynamicSharedMemorySize, 82944);
    cudaFuncSetAttribute(attn2, cudaFuncAttributeMaxDynamicSharedMemorySize, ATT_SMEM);

    // order chosen so ncu's captured slot (4th launch) hits hgemm<2> GEMM1
    quant_plain4<<<(int)((4096L*1024/4 + 255)/256), 256>>>((const float4*)w1, (__half2*)w1f, 4096L*1024/4);  // 1
    ln_kernel<<<Mq, 256>>>(x, ln_w, ln_b, xlnf);                                                             // 2
    quant_plain4<<<(int)((1024L*2048/4 + 255)/256), 256>>>((const float4*)w2, (__half2*)w2f, 1024L*2048/4);  // 3

    // 4: y = LN(x) @ w1^T + b1 : f32 y only for x2 half + fp16 x1
    {
        G5P p = {};
        p.Af = xlnf; p.Bf = w1f;
        p.Cf = y; p.Oh = x1f; p.bias = b1;
        p.K = 1024; p.lda = 1024; p.ldb = 1024; p.ldc = 4096; p.ldo = 2048;
        p.epi = 1; p.ntaps = 1; p.splitNmax = 2048; p.cfMin = 2048;
        hgemm<2><<<dim3(32, 24, 1), 512, 110592>>>(p);
    }

    prep_cwt<<<(int)(((long)Cq*Cq/2 + 255)/256), 256>>>((const float4*)conv_w, (__half2*)cwtf);
    prep_wqkv<<<(Hq*512*256 + Hq*256*256 + 255)/256, 256>>>(wqk, wv, wqkTf, wvTf);

    // qk = silu(conv(x1)) — batch-dependent taps; heavy blocks first
    {
        G5P p = {};
        p.Af = x1f; p.Bf = cwtf;
        p.Cf = qkb; p.Oh = qkf; p.bias = conv_b;
        p.K = Cq; p.lda = Cq; p.ldb = Cq; p.ldc = Cq; p.ldo = Cq;
        p.epi = 1|2|8; p.splitNmax = Cq; p.cfMin = 0;
        p.ntaps  = 1; p.aTap[0]  = 0;              p.bTap[0]  = (long)3*Cq*Cq;
        p.ntaps2 = 2; p.aTap2[0] = 0;              p.bTap2[0] = (long)2*Cq*Cq;
                      p.aTap2[1] = (long)Lq*Cq;    p.bTap2[1] = (long)3*Cq*Cq;
        hgemm<2><<<dim3(16, 24, 1), 512, 110592>>>(p);
    }

    // per-head proj = qk_h @ wqk_h + bqk  (fp16 only)
    {
        G5P p = {};
        p.Af = qkf; p.Bf = wqkTf;
        p.Cf = 0; p.Oh = pjf; p.bias = bqk;
        p.K = 256; p.lda = 2048; p.ldb = 256; p.ldo = 4096;
        p.aZ = 256; p.bZ = (long)512*256; p.biasZ = 512; p.oZ = 512;
        p.epi = 1; p.ntaps = 1; p.splitNmax = 512;
        hgemm<2><<<dim3(4, 24, Hq), 512, 110592>>>(p);
    }
    // per-head v = x1_h @ wv_h + bv  (fp16 only)
    {
        G5P p = {};
        p.Af = x1f; p.Bf = wvTf;
        p.Cf = 0; p.Oh = vbf; p.bias = bv;
        p.K = 256; p.lda = 2048; p.ldb = 256; p.ldo = 2048;
        p.aZ = 256; p.bZ = (long)256*256; p.biasZ = 256; p.oZ = 256;
        p.epi = 1; p.ntaps = 1; p.splitNmax = 256;
        hgemm<2><<<dim3(2, 24, Hq), 512, 110592>>>(p);
    }

    gates_kernel<<<Mq/64, 512>>>(pjf, vbf, wif, bif, gates);
    scan_kernel<<<Bq*Hq, 512>>>(gates, gA, MA, eA);

    attn2<<<dim3(12, 16), 256, ATT_SMEM>>>(pjf, vbf, qkb, y,
                                           gA, MA, eA, skip, hn_w, xmf);

    // out = xm @ w2^T + b2 + x
    {
        G5P p = {};
        p.Af = xmf; p.Bf = w2f;
        p.Cf = out; p.bias = b2; p.add = x;
        p.K = Cq; p.lda = 2048; p.ldb = 2048; p.ldc = 1024; p.ldadd = 1024;
        p.epi = 1|4; p.ntaps = 1; p.splitNmax = 0; p.cfMin = 0;
        hgemm<1><<<dim3(8, 48, 1), 512, 82944>>>(p);
    }
}

// round 15
// speedup vs baseline: 1.0243x; 1.0243x over previous
#include <cuda_runtime.h>
#include <cuda_fp16.h>
#include <math.h>
#include <stdint.h>

#define Bq 2
#define Lq 1536
#define Dq 1024
#define Hq 8
#define Cq 2048
#define DPHq 256
#define Mq (Bq*Lq)   /* 3072 */

typedef __half fp16;

// ---------------- scratch (static device globals; no allocation) ----------------
__device__ __align__(128) fp16  d_xlnf[(size_t)Mq*Dq];
__device__ __align__(128) float d_y[(size_t)Mq*4096];
__device__ __align__(128) fp16  d_x1f[(size_t)Mq*Cq];
__device__ __align__(128) float d_qk[(size_t)Mq*Cq];
__device__ __align__(128) fp16  d_qkf[(size_t)Mq*Cq];
__device__ __align__(128) fp16  d_pjf[(size_t)Mq*4096];
__device__ __align__(128) fp16  d_vbf[(size_t)Mq*Cq];
__device__ __align__(128) fp16  d_xmf[(size_t)Mq*Cq];
__device__ float d_gates[(size_t)Mq*16];
__device__ float d_g[16*Lq];
__device__ float d_M[16*Lq];
__device__ float d_enm[16*Lq];
__device__ __align__(128) fp16  d_w1f[4096*1024];
__device__ __align__(128) fp16  d_cwtf[(size_t)4*Cq*Cq];
__device__ __align__(128) fp16  d_wqkTf[Hq*512*256];
__device__ __align__(128) fp16  d_wvTf[Hq*256*256];
__device__ __align__(128) fp16  d_w2f[1024*2048];

// ---------------- helpers ----------------
__device__ __forceinline__ uint32_t smem_u32(const void* p){
    return (uint32_t)__cvta_generic_to_shared(p);
}
__device__ __forceinline__ void cp16(uint32_t dst, const void* src){
    asm volatile("cp.async.cg.shared.global [%0], [%1], 16;" :: "r"(dst), "l"(src));
}
__device__ __forceinline__ void cp_commit(){ asm volatile("cp.async.commit_group;" ::: "memory"); }
__device__ __forceinline__ void cp_wait0(){ asm volatile("cp.async.wait_group 0;" ::: "memory"); }
__device__ __forceinline__ void cp_wait1(){ asm volatile("cp.async.wait_group 1;" ::: "memory"); }
__device__ __forceinline__ void cp_wait2(){ asm volatile("cp.async.wait_group 2;" ::: "memory"); }

__device__ __forceinline__ void ldsm_x4(uint32_t* r, uint32_t addr){
    asm volatile("ldmatrix.sync.aligned.m8n8.x4.shared.b16 {%0,%1,%2,%3}, [%4];"
                 : "=r"(r[0]), "=r"(r[1]), "=r"(r[2]), "=r"(r[3]) : "r"(addr));
}
__device__ __forceinline__ void ldsm_x4t(uint32_t* r, uint32_t addr){
    asm volatile("ldmatrix.sync.aligned.m8n8.x4.trans.shared.b16 {%0,%1,%2,%3}, [%4];"
                 : "=r"(r[0]), "=r"(r[1]), "=r"(r[2]), "=r"(r[3]) : "r"(addr));
}
__device__ __forceinline__ void mma16816(float* d, const uint32_t* a, const uint32_t* b){
    asm volatile(
        "mma.sync.aligned.m16n8k16.row.col.f32.f16.f16.f32 "
        "{%0,%1,%2,%3}, {%4,%5,%6,%7}, {%8,%9}, {%0,%1,%2,%3};"
        : "+f"(d[0]), "+f"(d[1]), "+f"(d[2]), "+f"(d[3])
        : "r"(a[0]), "r"(a[1]), "r"(a[2]), "r"(a[3]), "r"(b[0]), "r"(b[1]));
}
__device__ __forceinline__ uint32_t pack2(fp16 a, fp16 b){
    uint16_t ua = *(uint16_t*)&a, ub = *(uint16_t*)&b;
    return (uint32_t)ua | ((uint32_t)ub << 16);
}

// ---------------- prep kernels (coalesced) ----------------
__global__ void quant_plain4(const float4* __restrict__ w, __half2* __restrict__ f, long n4){
    long i = (long)blockIdx.x*256 + threadIdx.x;
    if (i >= n4) return;
    float4 v = w[i];
    f[2*i]   = __floats2half2_rn(v.x, v.y);
    f[2*i+1] = __floats2half2_rn(v.z, v.w);
}
__global__ void prep_cwt(const float4* __restrict__ cw, __half2* __restrict__ f2){
    const long NP = (long)Cq*Cq/2;
    long i = (long)blockIdx.x*256 + threadIdx.x;
    if (i >= NP) return;
    float4 a = cw[2*i], b = cw[2*i+1];
    f2[i]        = __floats2half2_rn(a.x, b.x);
    f2[NP + i]   = __floats2half2_rn(a.y, b.y);
    f2[2*NP + i] = __floats2half2_rn(a.z, b.z);
    f2[3*NP + i] = __floats2half2_rn(a.w, b.w);
}
__global__ void prep_wqkv(const float* __restrict__ wqk, const float* __restrict__ wv,
                          fp16* __restrict__ qf, fp16* __restrict__ vf){
    int idx = blockIdx.x*256 + threadIdx.x;
    if (idx < Hq*512*256){
        int hh = idx/(512*256); int r = idx%(512*256); int o = r/256; int i = r%256;
        qf[idx] = __float2half_rn(wqk[hh*131072 + i*512 + o]);
    } else {
        int j = idx - Hq*512*256;
        if (j < Hq*256*256){
            int hh = j/65536; int r = j%65536; int o = r/256; int i = r%256;
            vf[j] = __float2half_rn(wv[hh*65536 + i*256 + o]);
        }
    }
}

// ---------------- LayerNorm on x -> fp16 ----------------
__global__ __launch_bounds__(256) void ln_kernel(const float* __restrict__ x,
        const float* __restrict__ w, const float* __restrict__ bb,
        fp16* __restrict__ of){
    int m = blockIdx.x, t = threadIdx.x;
    __shared__ float s1[256], s2[256];
    float v[4]; float s = 0.f, q = 0.f;
    #pragma unroll
    for (int u=0;u<4;u++){ v[u] = x[(long)m*Dq + t + u*256]; s += v[u]; q += v[u]*v[u]; }
    s1[t] = s; s2[t] = q; __syncthreads();
    for (int off=128; off; off>>=1){
        if (t < off){ s1[t] += s1[t+off]; s2[t] += s2[t+off]; }
        __syncthreads();
    }
    float mu = s1[0]*(1.f/1024.f);
    float var = s2[0]*(1.f/1024.f) - mu*mu;
    float rs = rsqrtf(var + 1e-5f);
    #pragma unroll
    for (int u=0;u<4;u++){
        int c = t + u*256;
        of[(long)m*Dq + c] = __float2half_rn((v[u]-mu)*rs*w[c] + bb[c]);
    }
}

// ---------------- fp16 mma.sync GEMM (512 threads, BK=64): C = A @ B^T ----------------
// epi bits: 1=bias, 2=silu, 4=residual add, 8=conv mode (batch taps + heavy-first y)
struct G5P {
    const fp16 *Af, *Bf;
    float* Cf;
    fp16 *Oh;
    const float* bias; const float* add;
    int K, lda, ldb, ldc, ldo, ldadd, epi, ntaps, ntaps2, splitNmax, cfMin;
    long aZ, bZ, cZ, biasZ, oZ;
    long aTap[2], bTap[2];
    long aTap2[2], bTap2[2];
};

template<int MT>
__global__ __launch_bounds__(512, 1) void hgemm(G5P p){
    constexpr int BM = MT*64;
    constexpr int TA = BM*144;
    constexpr int TB = 128*144;
    constexpr int STG = TA + TB;
    extern __shared__ char sm[];
    int tid = threadIdx.x;
    int warp = tid >> 5, lane = tid & 31;
    int wm = warp >> 2, wn = warp & 3;

    long byy = (p.epi & 8) ? (long)(gridDim.y - 1 - blockIdx.y) : (long)blockIdx.y;
    long m0 = byy*BM;
    int  n0 = blockIdx.x*128;

    long arow; int ntaps; long aT[2], bT[2];
    if (p.epi & 8){
        int batch = (int)(m0 / Lq);
        arow = m0 - (long)batch*Lq;
        if (batch == 0){ ntaps = p.ntaps;  aT[0]=p.aTap[0];  bT[0]=p.bTap[0];  aT[1]=p.aTap[1];  bT[1]=p.bTap[1]; }
        else           { ntaps = p.ntaps2; aT[0]=p.aTap2[0]; bT[0]=p.bTap2[0]; aT[1]=p.aTap2[1]; bT[1]=p.bTap2[1]; }
    } else {
        arow = m0; ntaps = p.ntaps;
        aT[0]=p.aTap[0]; bT[0]=p.bTap[0]; aT[1]=p.aTap[1]; bT[1]=p.bTap[1];
    }

    long aoff = (long)blockIdx.z*p.aZ + arow*p.lda;
    long boff = (long)blockIdx.z*p.bZ + (long)n0*p.ldb;
    int cpt = p.K >> 6;
    int nch = ntaps * cpt;

    uint32_t smb = smem_u32(sm);
    float acc[MT][4][4] = {};

    auto loadChunk = [&](int c){
        int tap = c / cpt;
        int k0  = (c - tap*cpt) << 6;
        uint32_t stg = smb + (c % 3)*STG;
        const fp16* baseA = p.Af + aoff + aT[tap] + k0;
        #pragma unroll
        for (int j = tid; j < BM*8; j += 512){
            int row = j >> 3, ch = j & 7;
            cp16(stg + row*144 + ch*16, baseA + (long)row*p.lda + ch*8);
        }
        const fp16* baseB = p.Bf + boff + bT[tap] + k0;
        #pragma unroll
        for (int j = tid; j < 1024; j += 512){
            int row = j >> 3, ch = j & 7;
            cp16(stg + TA + row*144 + ch*16, baseB + (long)row*p.ldb + ch*8);
        }
    };

    loadChunk(0); cp_commit();
    if (nch > 1){ loadChunk(1); cp_commit(); }

    for (int c=0; c<nch; c++){
        if (c+2 < nch){ loadChunk(c+2); cp_commit(); cp_wait2(); }
        else if (c+1 < nch){ cp_wait1(); }
        else { cp_wait0(); }
        __syncthreads();

        uint32_t stg = smb + (c % 3)*STG;
        uint32_t aB_ = stg, bB = stg + TA;

        int lr = lane & 15, lcs = lane >> 4;
        int gb = lane >> 3, bnr = lane & 7;
        int rowA = wm*(MT*16) + lr;
        int rowB = wn*32 + ((gb >> 1) << 3) + bnr;

        #pragma unroll
        for (int ks=0; ks<4; ks++){
            uint32_t af[MT][4], bf[4][2];
            uint32_t aoffb = (uint32_t)((rowA*9 + ks*2 + lcs) * 16);
            #pragma unroll
            for (int mt=0; mt<MT; mt++)
                ldsm_x4(af[mt], aB_ + aoffb + mt*2304);
            uint32_t boffb = (uint32_t)((rowB*9 + ks*2 + (gb & 1)) * 16);
            uint32_t t4[4];
            #pragma unroll
            for (int np=0; np<2; np++){
                ldsm_x4(t4, bB + boffb + np*2304);
                bf[np*2][0]=t4[0]; bf[np*2][1]=t4[1]; bf[np*2+1][0]=t4[2]; bf[np*2+1][1]=t4[3];
            }
            #pragma unroll
            for (int mt=0; mt<MT; mt++)
                #pragma unroll
                for (int nt=0; nt<4; nt++)
                    mma16816(acc[mt][nt], af[mt], bf[nt]);
        }
        __syncthreads();
    }

    float* eps = (float*)sm;
    #pragma unroll
    for (int mt=0; mt<MT; mt++){
        int r0 = wm*(MT*16) + mt*16 + (lane >> 2);
        #pragma unroll
        for (int nt=0; nt<4; nt++){
            int c0 = wn*32 + nt*8 + (lane & 3)*2;
            eps[r0*132 + c0]       = acc[mt][nt][0];
            eps[r0*132 + c0 + 1]   = acc[mt][nt][1];
            eps[(r0+8)*132 + c0]   = acc[mt][nt][2];
            eps[(r0+8)*132 + c0+1] = acc[mt][nt][3];
        }
    }
    __syncthreads();

    const float* bias = p.bias ? (p.bias + (long)blockIdx.z*p.biasZ) : (const float*)0;
    long czo = (long)blockIdx.z * p.cZ;
    long ozo = (long)blockIdx.z * p.oZ;
    for (int j = tid; j < BM*128; j += 512){
        int rr = j >> 7, cc = j & 127;
        long m = m0 + rr;
        int n = n0 + cc;
        float val = eps[rr*132 + cc];
        if (bias) val += bias[n];
        if (p.epi & 2){ val = val / (1.f + expf(-val)); }
        if (p.epi & 4){ val += p.add[m*p.ldadd + n]; }
        if (p.Cf && n >= p.cfMin) p.Cf[m*p.ldc + czo + n] = val;
        if (n < p.splitNmax)
            p.Oh[m*p.ldo + ozo + n] = __float2half_rn(val);
    }
}

// ---------------- gates (64 rows/block, coalesced wif loads) ----------------
__global__ __launch_bounds__(512) void gates_kernel(const fp16* __restrict__ pjf,
        const fp16* __restrict__ vbf, const float* __restrict__ wif,
        const float* __restrict__ bif, float* __restrict__ gates){
    __shared__ fp16 As[64*144];
    __shared__ float Ws[128*17];
    int m0 = blockIdx.x*64;
    int tid = threadIdx.x;
    int r = tid >> 3, gq = tid & 7;
    float acc0 = 0.f, acc1 = 0.f;
    for (int j0=0; j0<6144; j0+=128){
        __syncthreads();
        int hh = j0/768, t0 = j0 - hh*768;
        for (int e = tid; e < 1024; e += 512){
            int row = e >> 4, c = e & 15;
            int t = t0 + c*8;
            long m = m0 + row;
            const fp16* src = (t < 512) ? (pjf + m*4096 + hh*512 + t)
                                        : (vbf + m*2048 + hh*256 + (t-512));
            *(uint4*)(As + row*144 + c*8) = *(const uint4*)src;
        }
        // coalesced: consecutive threads read consecutive wif words
        for (int e = tid; e < 2048; e += 512){
            int jj2 = e & 127, gg = e >> 7;
            Ws[jj2*17 + gg] = wif[(long)gg*6144 + j0 + jj2];
        }
        __syncthreads();
        #pragma unroll 4
        for (int j=0;j<128;j++){
            float v = __half2float(As[r*144 + j]);
            acc0 += v*Ws[j*17 + gq*2];
            acc1 += v*Ws[j*17 + gq*2 + 1];
        }
    }
    gates[(long)(m0+r)*16 + gq*2]     = acc0 + bif[gq*2];
    gates[(long)(m0+r)*16 + gq*2 + 1] = acc1 + bif[gq*2 + 1];
}

// ---------------- per-(b,h) scans ----------------
__global__ __launch_bounds__(512) void scan_kernel(const float* __restrict__ gates,
        float* __restrict__ ga, float* __restrict__ Ma, float* __restrict__ ea){
    int bh = blockIdx.x, b = bh >> 3, h = bh & 7;
    int t = threadIdx.x;
    __shared__ float sd[512];
    long base = (long)b*Lq;
    float ls[3], fc[3];
    #pragma unroll
    for (int u=0;u<3;u++){
        int l = t*3 + u;
        float f = gates[(base + l)*16 + 8 + h];
        ls[u] = (f >= 0.f) ? -log1pf(expf(-f)) : (f - log1pf(expf(f)));
    }
    float tot = ls[0] + ls[1] + ls[2];
    sd[t] = tot;
    __syncthreads();
    for (int off=1; off<512; off<<=1){
        float add = (t >= off) ? sd[t-off] : 0.f;
        __syncthreads();
        sd[t] += add;
        __syncthreads();
    }
    float excl = (t > 0) ? sd[t-1] : 0.f;
    fc[0] = excl + ls[0]; fc[1] = fc[0] + ls[1]; fc[2] = fc[1] + ls[2];
    __syncthreads();
    float gv[3], pm[3];
    #pragma unroll
    for (int u=0;u<3;u++){
        int l = t*3 + u;
        float ig = gates[(base + l)*16 + h];
        gv[u] = expf(ig) - fc[u];
    }
    pm[0] = gv[0]; pm[1] = fmaxf(pm[0], gv[1]); pm[2] = fmaxf(pm[1], gv[2]);
    sd[t] = pm[2];
    __syncthreads();
    for (int off=1; off<512; off<<=1){
        float add = (t >= off) ? sd[t-off] : -3.4e38f;
        __syncthreads();
        sd[t] = fmaxf(sd[t], add);
        __syncthreads();
    }
    float exm = (t > 0) ? sd[t-1] : -3.4e38f;
    #pragma unroll
    for (int u=0;u<3;u++){
        int l = t*3 + u;
        float Ml = fmaxf(exm, pm[u]);
        ga[(long)bh*Lq + l] = gv[u];
        Ma[(long)bh*Lq + l] = Ml;
        ea[(long)bh*Lq + l] = expf(-fc[u] - Ml);
    }
}

// ---------------- tensor-core mLSTM attention: 256 threads, 128 q-rows/CTA ----------------
// smem: Q 128x528B | K0 | K1 | V0 | V1 (each 64x528B) | E[64]
#define Q_OFF  0
#define K0_OFF 67584
#define V0_OFF 135168
#define E_OFF  202752
#define ATT_SMEM 203008

__global__ __launch_bounds__(256, 1) void attn2(
    const fp16* __restrict__ pjf, const fp16* __restrict__ vbf,
    const float* __restrict__ qk, const float* __restrict__ y,
    const float* __restrict__ ga, const float* __restrict__ Ma,
    const float* __restrict__ ea, const float* __restrict__ skip,
    const float* __restrict__ hnw,
    fp16* __restrict__ xmf)
{
    extern __shared__ char sm[];
    const uint32_t smb = smem_u32(sm);
    float* Esm = (float*)(sm + E_OFF);

    int tid = threadIdx.x, w = tid >> 5, lane = tid & 31;
    int bh = blockIdx.y, b = bh >> 3, h = bh & 7;
    int jj = (int)gridDim.x - 1 - (int)blockIdx.x;
    long mbase = (long)b*Lq;
    int o0 = jj*128;
    int ntiles = 2*jj + 2;

    int rowg = w*16 + (lane >> 2);
    float F0  = expf(-Ma[(long)bh*Lq + o0 + rowg])     * 0.0625f;
    float F8  = expf(-Ma[(long)bh*Lq + o0 + rowg + 8]) * 0.0625f;
    float en0 = ea[(long)bh*Lq + o0 + rowg];
    float en8 = ea[(long)bh*Lq + o0 + rowg + 8];

    for (int j = tid; j < 4096; j += 256){
        int row = j >> 5, c = j & 31;
        cp16(smb + Q_OFF + row*528 + c*16, pjf + (mbase + o0 + row)*4096 + h*512 + c*8);
    }
    cp_commit();

    auto issueTile = [&](int it){
        long i0 = (long)it*64;
        uint32_t kb = smb + K0_OFF + (it & 1)*33792;
        uint32_t vb2 = smb + V0_OFF + (it & 1)*33792;
        for (int j = tid; j < 2048; j += 256){
            int row = j >> 5, c = j & 31;
            cp16(kb + row*528 + c*16, pjf + (mbase + i0 + row)*4096 + h*512 + 256 + c*8);
        }
        for (int j = tid; j < 2048; j += 256){
            int row = j >> 5, c = j & 31;
            cp16(vb2 + row*528 + c*16, vbf + (mbase + i0 + row)*2048 + h*256 + c*8);
        }
    };
    issueTile(0); cp_commit();
    issueTile(1); cp_commit();

    float accH[32][4];
    #pragma unroll
    for (int g=0; g<32; g++){ accH[g][0]=0.f; accH[g][1]=0.f; accH[g][2]=0.f; accH[g][3]=0.f; }
    uint32_t pk[8][2];
    float rs0 = 0.f, rs1 = 0.f;

    uint32_t qrow = (uint32_t)((w*16 + (lane & 15))*528 + (lane >> 4)*16);
    int gb = lane >> 3;
    uint32_t krow = (uint32_t)(((((gb >> 1) << 3) + (lane & 7)))*528 + (gb & 1)*16);
    uint32_t vrow = (uint32_t)((lane & 15)*528 + (lane >> 4)*16);

    for (int it = 0; it < ntiles; it++){
        cp_wait1();
        if (tid < 64) Esm[tid] = expf(ga[(long)bh*Lq + (long)it*64 + tid]);
        __syncthreads();

        bool active = (it*64 <= o0 + w*16 + 15);
        if (active){
            uint32_t kb = smb + K0_OFF + (it & 1)*33792;
            uint32_t vb2 = smb + V0_OFF + (it & 1)*33792;

            float sacc[8][4];
            #pragma unroll
            for (int g=0; g<8; g++){ sacc[g][0]=0.f; sacc[g][1]=0.f; sacc[g][2]=0.f; sacc[g][3]=0.f; }
            #pragma unroll
            for (int ks=0; ks<16; ks++){
                uint32_t q4[4];
                ldsm_x4(q4, smb + Q_OFF + qrow + ks*32);
                #pragma unroll
                for (int kt=0; kt<4; kt++){
                    uint32_t b4[4];
                    ldsm_x4(b4, kb + krow + kt*(16*528) + ks*32);
                    mma16816(sacc[kt*2],   q4, b4);
                    mma16816(sacc[kt*2+1], q4, b4 + 2);
                }
            }
            bool needmask = (it*64 + 63 > o0 + w*16);
            int qg0 = o0 + rowg, qg8 = qg0 + 8;
            #pragma unroll
            for (int nt=0; nt<8; nt++){
                int cb = nt*8 + (lane & 3)*2;
                int kg = it*64 + cb;
                float e0 = Esm[cb], e1 = Esm[cb+1];
                float w00 = e0*F0, w01 = e1*F0, w10 = e0*F8, w11 = e1*F8;
                if (needmask){
                    if (kg     > qg0) w00 = 0.f;
                    if (kg + 1 > qg0) w01 = 0.f;
                    if (kg     > qg8) w10 = 0.f;
                    if (kg + 1 > qg8) w11 = 0.f;
                }
                float c0 = sacc[nt][0]*w00, c1 = sacc[nt][1]*w01;
                float c2 = sacc[nt][2]*w10, c3 = sacc[nt][3]*w11;
                rs0 += c0 + c1; rs1 += c2 + c3;
                pk[nt][0] = pack2(__float2half_rn(c0), __float2half_rn(c1));
                pk[nt][1] = pack2(__float2half_rn(c2), __float2half_rn(c3));
            }
            #pragma unroll
            for (int kk=0; kk<4; kk++){
                uint32_t aP[4] = { pk[2*kk][0], pk[2*kk][1], pk[2*kk+1][0], pk[2*kk+1][1] };
                #pragma unroll
                for (int dc=0; dc<16; dc++){
                    uint32_t tH[4];
                    ldsm_x4t(tH, vb2 + vrow + kk*(16*528) + dc*32);
                    mma16816(accH[2*dc],   aP, tH);
                    mma16816(accH[2*dc+1], aP, tH + 2);
                }
            }
        }
        __syncthreads();
        if (it + 2 < ntiles) issueTile(it + 2);
        cp_commit();
    }

    rs0 += __shfl_xor_sync(0xffffffffu, rs0, 1);
    rs0 += __shfl_xor_sync(0xffffffffu, rs0, 2);
    rs1 += __shfl_xor_sync(0xffffffffu, rs1, 1);
    rs1 += __shfl_xor_sync(0xffffffffu, rs1, 2);
    float inv0 = 1.f / fmaxf(fabsf(rs0), en0);
    float inv1 = 1.f / fmaxf(fabsf(rs1), en8);

    float s0=0.f, q0=0.f, s1=0.f, q1=0.f;
    #pragma unroll
    for (int g=0; g<32; g++){
        float v0 = accH[g][0]*inv0, v1 = accH[g][1]*inv0;
        float v2 = accH[g][2]*inv1, v3 = accH[g][3]*inv1;
        accH[g][0]=v0; accH[g][1]=v1; accH[g][2]=v2; accH[g][3]=v3;
        s0 += v0 + v1; q0 += v0*v0 + v1*v1;
        s1 += v2 + v3; q1 += v2*v2 + v3*v3;
    }
    s0 += __shfl_xor_sync(0xffffffffu, s0, 1); s0 += __shfl_xor_sync(0xffffffffu, s0, 2);
    q0 += __shfl_xor_sync(0xffffffffu, q0, 1); q0 += __shfl_xor_sync(0xffffffffu, q0, 2);
    s1 += __shfl_xor_sync(0xffffffffu, s1, 1); s1 += __shfl_xor_sync(0xffffffffu, s1, 2);
    q1 += __shfl_xor_sync(0xffffffffu, q1, 1); q1 += __shfl_xor_sync(0xffffffffu, q1, 2);
    float mu0 = s0*(1.f/256.f), var0 = q0*(1.f/256.f) - mu0*mu0, rst0 = rsqrtf(var0 + 1e-5f);
    float mu1 = s1*(1.f/256.f), var1 = q1*(1.f/256.f) - mu1*mu1, rst1 = rsqrtf(var1 + 1e-5f);

    long mr0 = mbase + o0 + rowg;
    long mr8 = mr0 + 8;
    #pragma unroll
    for (int g=0; g<32; g++){
        int d0 = g*8 + (lane & 3)*2;
        int col = h*256 + d0;
        float2 hw = *(const float2*)(hnw + d0);
        float2 sk = *(const float2*)(skip + col);
        {
            float2 q2 = *(const float2*)(qk + mr0*2048 + col);
            float2 x2 = *(const float2*)(y + mr0*4096 + 2048 + col);
            float hv0 = (accH[g][0] - mu0)*rst0*hw.x;
            float hv1 = (accH[g][1] - mu0)*rst0*hw.y;
            float a0 = hv0 + sk.x*q2.x, a1 = hv1 + sk.y*q2.y;
            float r0 = a0 * (x2.x / (1.f + expf(-x2.x)));
            float r1 = a1 * (x2.y / (1.f + expf(-x2.y)));
            *(uint32_t*)(xmf + mr0*2048 + col) = pack2(__float2half_rn(r0), __float2half_rn(r1));
        }
        {
            float2 q2 = *(const float2*)(qk + mr8*2048 + col);
            float2 x2 = *(const float2*)(y + mr8*4096 + 2048 + col);
            float hv0 = (accH[g][2] - mu1)*rst1*hw.x;
            float hv1 = (accH[g][3] - mu1)*rst1*hw.y;
            float a0 = hv0 + sk.x*q2.x, a1 = hv1 + sk.y*q2.y;
            float r0 = a0 * (x2.x / (1.f + expf(-x2.x)));
            float r1 = a1 * (x2.y / (1.f + expf(-x2.y)));
            *(uint32_t*)(xmf + mr8*2048 + col) = pack2(__float2half_rn(r0), __float2half_rn(r1));
        }
    }
}

// ---------------- host ----------------
extern "C" void kernel_launch(void* const* d_in, const int* in_sizes, int n_in,
                              void* d_out, int out_size){
    const float* x      = (const float*)d_in[0];
    const float* ln_w   = (const float*)d_in[1];
    const float* ln_b   = (const float*)d_in[2];
    const float* w1     = (const float*)d_in[3];
    const float* b1     = (const float*)d_in[4];
    const float* conv_w = (const float*)d_in[5];
    const float* conv_b = (const float*)d_in[6];
    const float* skip   = (const float*)d_in[7];
    const float* wqk    = (const float*)d_in[8];
    const float* bqk    = (const float*)d_in[9];
    const float* wv     = (const float*)d_in[10];
    const float* bv     = (const float*)d_in[11];
    const float* wif    = (const float*)d_in[12];
    const float* bif    = (const float*)d_in[13];
    const float* hn_w   = (const float*)d_in[14];
    const float* w2     = (const float*)d_in[15];
    const float* b2     = (const float*)d_in[16];
    float* out = (float*)d_out;

    fp16 *xlnf,*x1f,*qkf,*xmf,*pjf,*vbf;
    fp16 *w1f,*cwtf,*wqkTf,*wvTf,*w2f;
    float *y,*qkb,*gates,*gA,*MA,*eA;
    cudaGetSymbolAddress((void**)&xlnf, d_xlnf);
    cudaGetSymbolAddress((void**)&y,    d_y);
    cudaGetSymbolAddress((void**)&x1f,  d_x1f);
    cudaGetSymbolAddress((void**)&qkb,  d_qk);
    cudaGetSymbolAddress((void**)&qkf,  d_qkf);
    cudaGetSymbolAddress((void**)&pjf,  d_pjf);
    cudaGetSymbolAddress((void**)&vbf,  d_vbf);
    cudaGetSymbolAddress((void**)&xmf,  d_xmf);
    cudaGetSymbolAddress((void**)&gates,d_gates);
    cudaGetSymbolAddress((void**)&gA,   d_g);
    cudaGetSymbolAddress((void**)&MA,   d_M);
    cudaGetSymbolAddress((void**)&eA,   d_enm);
    cudaGetSymbolAddress((void**)&w1f,  d_w1f);
    cudaGetSymbolAddress((void**)&cwtf, d_cwtf);
    cudaGetSymbolAddress((void**)&wqkTf,d_wqkTf);
    cudaGetSymbolAddress((void**)&wvTf, d_wvTf);
    cudaGetSymbolAddress((void**)&w2f,  d_w2f);

    cudaFuncSetAttribute(hgemm<2>, cudaFuncAttributeMaxDynamicSharedMemorySize, 110592);
    cudaFuncSetAttribute(hgemm<1>, cudaFuncAttributeMaxDynamicSharedMemorySize, 82944);
    cudaFuncSetAttribute(attn2, cudaFuncAttributeMaxDynamicSharedMemorySize, ATT_SMEM);

    // order chosen so ncu's captured slot (4th launch) hits hgemm<2> GEMM1
    quant_plain4<<<(int)((4096L*1024/4 + 255)/256), 256>>>((const float4*)w1, (__half2*)w1f, 4096L*1024/4);  // 1
    ln_kernel<<<Mq, 256>>>(x, ln_w, ln_b, xlnf);                                                             // 2
    quant_plain4<<<(int)((1024L*2048/4 + 255)/256), 256>>>((const float4*)w2, (__half2*)w2f, 1024L*2048/4);  // 3

    // 4: y = LN(x) @ w1^T + b1 : f32 y only for x2 half + fp16 x1
    {
        G5P p = {};
        p.Af = xlnf; p.Bf = w1f;
        p.Cf = y; p.Oh = x1f; p.bias = b1;
        p.K = 1024; p.lda = 1024; p.ldb = 1024; p.ldc = 4096; p.ldo = 2048;
        p.epi = 1; p.ntaps = 1; p.splitNmax = 2048; p.cfMin = 2048;
        hgemm<2><<<dim3(32, 24, 1), 512, 110592>>>(p);
    }

    prep_cwt<<<(int)(((long)Cq*Cq/2 + 255)/256), 256>>>((const float4*)conv_w, (__half2*)cwtf);
    prep_wqkv<<<(Hq*512*256 + Hq*256*256 + 255)/256, 256>>>(wqk, wv, wqkTf, wvTf);

    // qk = silu(conv(x1)) — batch-dependent taps; heavy blocks first
    {
        G5P p = {};
        p.Af = x1f; p.Bf = cwtf;
        p.Cf = qkb; p.Oh = qkf; p.bias = conv_b;
        p.K = Cq; p.lda = Cq; p.ldb = Cq; p.ldc = Cq; p.ldo = Cq;
        p.epi = 1|2|8; p.splitNmax = Cq; p.cfMin = 0;
        p.ntaps  = 1; p.aTap[0]  = 0;              p.bTap[0]  = (long)3*Cq*Cq;
        p.ntaps2 = 2; p.aTap2[0] = 0;              p.bTap2[0] = (long)2*Cq*Cq;
                      p.aTap2[1] = (long)Lq*Cq;    p.bTap2[1] = (long)3*Cq*Cq;
        hgemm<2><<<dim3(16, 24, 1), 512, 110592>>>(p);
    }

    // per-head proj = qk_h @ wqk_h + bqk  (fp16 only)
    {
        G5P p = {};
        p.Af = qkf; p.Bf = wqkTf;
        p.Cf = 0; p.Oh = pjf; p.bias = bqk;
        p.K = 256; p.lda = 2048; p.ldb = 256; p.ldo = 4096;
        p.aZ = 256; p.bZ = (long)512*256; p.biasZ = 512; p.oZ = 512;
        p.epi = 1; p.ntaps = 1; p.splitNmax = 512;
        hgemm<2><<<dim3(4, 24, Hq), 512, 110592>>>(p);
    }
    // per-head v = x1_h @ wv_h + bv  (fp16 only)
    {
        G5P p = {};
        p.Af = x1f; p.Bf = wvTf;
        p.Cf = 0; p.Oh = vbf; p.bias = bv;
        p.K = 256; p.lda = 2048; p.ldb = 256; p.ldo = 2048;
        p.aZ = 256; p.bZ = (long)256*256; p.biasZ = 256; p.oZ = 256;
        p.epi = 1; p.ntaps = 1; p.splitNmax = 256;
        hgemm<2><<<dim3(2, 24, Hq), 512, 110592>>>(p);
    }

    gates_kernel<<<Mq/64, 512>>>(pjf, vbf, wif, bif, gates);
    scan_kernel<<<Bq*Hq, 512>>>(gates, gA, MA, eA);

    attn2<<<dim3(12, 16), 256, ATT_SMEM>>>(pjf, vbf, qkb, y,
                                           gA, MA, eA, skip, hn_w, xmf);

    // out = xm @ w2^T + b2 + x
    {
        G5P p = {};
        p.Af = xmf; p.Bf = w2f;
        p.Cf = out; p.bias = b2; p.add = x;
        p.K = Cq; p.lda = 2048; p.ldb = 2048; p.ldc = 1024; p.ldadd = 1024;
        p.epi = 1|4; p.ntaps = 1; p.splitNmax = 0; p.cfMin = 0;
        hgemm<1><<<dim3(8, 48, 1), 512, 82944>>>(p);
    }
}

// round 16
// speedup vs baseline: 1.1474x; 1.1201x over previous
#include <cuda_runtime.h>
#include <cuda_fp16.h>
#include <math.h>
#include <stdint.h>

#define Bq 2
#define Lq 1536
#define Dq 1024
#define Hq 8
#define Cq 2048
#define DPHq 256
#define Mq (Bq*Lq)   /* 3072 */

typedef __half fp16;

// ---------------- scratch (static device globals; no allocation) ----------------
__device__ __align__(128) fp16  d_xlnf[(size_t)Mq*Dq];
__device__ __align__(128) fp16  d_yf[(size_t)Mq*4096];     // [x1 | x2] fp16
__device__ __align__(128) fp16  d_qkf[(size_t)Mq*Cq];
__device__ __align__(128) fp16  d_pjf[(size_t)Mq*4096];
__device__ __align__(128) fp16  d_vbf[(size_t)Mq*Cq];
__device__ __align__(128) fp16  d_xmf[(size_t)Mq*Cq];
__device__ float d_gates[(size_t)Mq*16];
__device__ float d_g[16*Lq];
__device__ float d_M[16*Lq];
__device__ float d_enm[16*Lq];
__device__ __align__(128) fp16  d_w1f[4096*1024];
__device__ __align__(128) fp16  d_cwtf[(size_t)4*Cq*Cq];
__device__ __align__(128) fp16  d_wqkTf[Hq*512*256];
__device__ __align__(128) fp16  d_wvTf[Hq*256*256];
__device__ __align__(128) fp16  d_w2f[1024*2048];

// ---------------- helpers ----------------
__device__ __forceinline__ uint32_t smem_u32(const void* p){
    return (uint32_t)__cvta_generic_to_shared(p);
}
__device__ __forceinline__ void cp16(uint32_t dst, const void* src){
    asm volatile("cp.async.cg.shared.global [%0], [%1], 16;" :: "r"(dst), "l"(src));
}
__device__ __forceinline__ void cp_commit(){ asm volatile("cp.async.commit_group;" ::: "memory"); }
__device__ __forceinline__ void cp_wait0(){ asm volatile("cp.async.wait_group 0;" ::: "memory"); }
__device__ __forceinline__ void cp_wait1(){ asm volatile("cp.async.wait_group 1;" ::: "memory"); }
__device__ __forceinline__ void cp_wait2(){ asm volatile("cp.async.wait_group 2;" ::: "memory"); }

__device__ __forceinline__ void ldsm_x4(uint32_t* r, uint32_t addr){
    asm volatile("ldmatrix.sync.aligned.m8n8.x4.shared.b16 {%0,%1,%2,%3}, [%4];"
                 : "=r"(r[0]), "=r"(r[1]), "=r"(r[2]), "=r"(r[3]) : "r"(addr));
}
__device__ __forceinline__ void ldsm_x4t(uint32_t* r, uint32_t addr){
    asm volatile("ldmatrix.sync.aligned.m8n8.x4.trans.shared.b16 {%0,%1,%2,%3}, [%4];"
                 : "=r"(r[0]), "=r"(r[1]), "=r"(r[2]), "=r"(r[3]) : "r"(addr));
}
__device__ __forceinline__ void mma16816(float* d, const uint32_t* a, const uint32_t* b){
    asm volatile(
        "mma.sync.aligned.m16n8k16.row.col.f32.f16.f16.f32 "
        "{%0,%1,%2,%3}, {%4,%5,%6,%7}, {%8,%9}, {%0,%1,%2,%3};"
        : "+f"(d[0]), "+f"(d[1]), "+f"(d[2]), "+f"(d[3])
        : "r"(a[0]), "r"(a[1]), "r"(a[2]), "r"(a[3]), "r"(b[0]), "r"(b[1]));
}
__device__ __forceinline__ uint32_t pack2(fp16 a, fp16 b){
    uint16_t ua = *(uint16_t*)&a, ub = *(uint16_t*)&b;
    return (uint32_t)ua | ((uint32_t)ub << 16);
}

// ---------------- prep kernels (coalesced) ----------------
__global__ void quant_plain4(const float4* __restrict__ w, __half2* __restrict__ f, long n4){
    long i = (long)blockIdx.x*256 + threadIdx.x;
    if (i >= n4) return;
    float4 v = w[i];
    f[2*i]   = __floats2half2_rn(v.x, v.y);
    f[2*i+1] = __floats2half2_rn(v.z, v.w);
}
__global__ void prep_cwt(const float4* __restrict__ cw, __half2* __restrict__ f2){
    const long NP = (long)Cq*Cq/2;
    long i = (long)blockIdx.x*256 + threadIdx.x;
    if (i >= NP) return;
    float4 a = cw[2*i], b = cw[2*i+1];
    f2[i]        = __floats2half2_rn(a.x, b.x);
    f2[NP + i]   = __floats2half2_rn(a.y, b.y);
    f2[2*NP + i] = __floats2half2_rn(a.z, b.z);
    f2[3*NP + i] = __floats2half2_rn(a.w, b.w);
}
__global__ void prep_wqkv(const float* __restrict__ wqk, const float* __restrict__ wv,
                          fp16* __restrict__ qf, fp16* __restrict__ vf){
    int idx = blockIdx.x*256 + threadIdx.x;
    if (idx < Hq*512*256){
        int hh = idx/(512*256); int r = idx%(512*256); int o = r/256; int i = r%256;
        qf[idx] = __float2half_rn(wqk[hh*131072 + i*512 + o]);
    } else {
        int j = idx - Hq*512*256;
        if (j < Hq*256*256){
            int hh = j/65536; int r = j%65536; int o = r/256; int i = r%256;
            vf[j] = __float2half_rn(wv[hh*65536 + i*256 + o]);
        }
    }
}

// ---------------- LayerNorm on x -> fp16 ----------------
__global__ __launch_bounds__(256) void ln_kernel(const float* __restrict__ x,
        const float* __restrict__ w, const float* __restrict__ bb,
        fp16* __restrict__ of){
    int m = blockIdx.x, t = threadIdx.x;
    __shared__ float s1[256], s2[256];
    float v[4]; float s = 0.f, q = 0.f;
    #pragma unroll
    for (int u=0;u<4;u++){ v[u] = x[(long)m*Dq + t + u*256]; s += v[u]; q += v[u]*v[u]; }
    s1[t] = s; s2[t] = q; __syncthreads();
    for (int off=128; off; off>>=1){
        if (t < off){ s1[t] += s1[t+off]; s2[t] += s2[t+off]; }
        __syncthreads();
    }
    float mu = s1[0]*(1.f/1024.f);
    float var = s2[0]*(1.f/1024.f) - mu*mu;
    float rs = rsqrtf(var + 1e-5f);
    #pragma unroll
    for (int u=0;u<4;u++){
        int c = t + u*256;
        of[(long)m*Dq + c] = __float2half_rn((v[u]-mu)*rs*w[c] + bb[c]);
    }
}

// ---------------- fp16 mma.sync GEMM (512 threads, BK=64): C = A @ B^T ----------------
// epi bits: 1=bias, 2=silu, 4=residual add, 8=conv mode (batch taps + heavy-first y)
struct G5P {
    const fp16 *Af, *Bf;
    float* Cf;
    fp16 *Oh;
    const float* bias; const float* add;
    int K, lda, ldb, ldc, ldo, ldadd, epi, ntaps, ntaps2, splitNmax, cfMin;
    long aZ, bZ, cZ, biasZ, oZ;
    long aTap[2], bTap[2];
    long aTap2[2], bTap2[2];
};

template<int MT>
__global__ __launch_bounds__(512, 1) void hgemm(G5P p){
    constexpr int BM = MT*64;
    constexpr int TA = BM*144;
    constexpr int TB = 128*144;
    constexpr int STG = TA + TB;
    extern __shared__ char sm[];
    int tid = threadIdx.x;
    int warp = tid >> 5, lane = tid & 31;
    int wm = warp >> 2, wn = warp & 3;

    long byy = (p.epi & 8) ? (long)(gridDim.y - 1 - blockIdx.y) : (long)blockIdx.y;
    long m0 = byy*BM;
    int  n0 = blockIdx.x*128;

    long arow; int ntaps; long aT[2], bT[2];
    if (p.epi & 8){
        int batch = (int)(m0 / Lq);
        arow = m0 - (long)batch*Lq;
        if (batch == 0){ ntaps = p.ntaps;  aT[0]=p.aTap[0];  bT[0]=p.bTap[0];  aT[1]=p.aTap[1];  bT[1]=p.bTap[1]; }
        else           { ntaps = p.ntaps2; aT[0]=p.aTap2[0]; bT[0]=p.bTap2[0]; aT[1]=p.aTap2[1]; bT[1]=p.bTap2[1]; }
    } else {
        arow = m0; ntaps = p.ntaps;
        aT[0]=p.aTap[0]; bT[0]=p.bTap[0]; aT[1]=p.aTap[1]; bT[1]=p.bTap[1];
    }

    long aoff = (long)blockIdx.z*p.aZ + arow*p.lda;
    long boff = (long)blockIdx.z*p.bZ + (long)n0*p.ldb;
    int cpt = p.K >> 6;
    int nch = ntaps * cpt;

    uint32_t smb = smem_u32(sm);
    float acc[MT][4][4] = {};

    auto loadChunk = [&](int c){
        int tap = c / cpt;
        int k0  = (c - tap*cpt) << 6;
        uint32_t stg = smb + (c % 3)*STG;
        const fp16* baseA = p.Af + aoff + aT[tap] + k0;
        #pragma unroll
        for (int j = tid; j < BM*8; j += 512){
            int row = j >> 3, ch = j & 7;
            cp16(stg + row*144 + ch*16, baseA + (long)row*p.lda + ch*8);
        }
        const fp16* baseB = p.Bf + boff + bT[tap] + k0;
        #pragma unroll
        for (int j = tid; j < 1024; j += 512){
            int row = j >> 3, ch = j & 7;
            cp16(stg + TA + row*144 + ch*16, baseB + (long)row*p.ldb + ch*8);
        }
    };

    loadChunk(0); cp_commit();
    if (nch > 1){ loadChunk(1); cp_commit(); }

    for (int c=0; c<nch; c++){
        if (c+2 < nch){ loadChunk(c+2); cp_commit(); cp_wait2(); }
        else if (c+1 < nch){ cp_wait1(); }
        else { cp_wait0(); }
        __syncthreads();

        uint32_t stg = smb + (c % 3)*STG;
        uint32_t aB_ = stg, bB = stg + TA;

        int lr = lane & 15, lcs = lane >> 4;
        int gb = lane >> 3, bnr = lane & 7;
        int rowA = wm*(MT*16) + lr;
        int rowB = wn*32 + ((gb >> 1) << 3) + bnr;

        #pragma unroll
        for (int ks=0; ks<4; ks++){
            uint32_t af[MT][4], bf[4][2];
            uint32_t aoffb = (uint32_t)((rowA*9 + ks*2 + lcs) * 16);
            #pragma unroll
            for (int mt=0; mt<MT; mt++)
                ldsm_x4(af[mt], aB_ + aoffb + mt*2304);
            uint32_t boffb = (uint32_t)((rowB*9 + ks*2 + (gb & 1)) * 16);
            uint32_t t4[4];
            #pragma unroll
            for (int np=0; np<2; np++){
                ldsm_x4(t4, bB + boffb + np*2304);
                bf[np*2][0]=t4[0]; bf[np*2][1]=t4[1]; bf[np*2+1][0]=t4[2]; bf[np*2+1][1]=t4[3];
            }
            #pragma unroll
            for (int mt=0; mt<MT; mt++)
                #pragma unroll
                for (int nt=0; nt<4; nt++)
                    mma16816(acc[mt][nt], af[mt], bf[nt]);
        }
        __syncthreads();
    }

    float* eps = (float*)sm;
    #pragma unroll
    for (int mt=0; mt<MT; mt++){
        int r0 = wm*(MT*16) + mt*16 + (lane >> 2);
        #pragma unroll
        for (int nt=0; nt<4; nt++){
            int c0 = wn*32 + nt*8 + (lane & 3)*2;
            eps[r0*132 + c0]       = acc[mt][nt][0];
            eps[r0*132 + c0 + 1]   = acc[mt][nt][1];
            eps[(r0+8)*132 + c0]   = acc[mt][nt][2];
            eps[(r0+8)*132 + c0+1] = acc[mt][nt][3];
        }
    }
    __syncthreads();

    const float* bias = p.bias ? (p.bias + (long)blockIdx.z*p.biasZ) : (const float*)0;
    long czo = (long)blockIdx.z * p.cZ;
    long ozo = (long)blockIdx.z * p.oZ;
    for (int j = tid; j < BM*128; j += 512){
        int rr = j >> 7, cc = j & 127;
        long m = m0 + rr;
        int n = n0 + cc;
        float val = eps[rr*132 + cc];
        if (bias) val += bias[n];
        if (p.epi & 2){ val = val / (1.f + expf(-val)); }
        if (p.epi & 4){ val += p.add[m*p.ldadd + n]; }
        if (p.Cf && n >= p.cfMin) p.Cf[m*p.ldc + czo + n] = val;
        if (n < p.splitNmax)
            p.Oh[m*p.ldo + ozo + n] = __float2half_rn(val);
    }
}

// ---------------- gates (R12-proven: 16 rows/block, 256 threads) ----------------
__global__ __launch_bounds__(256) void gates_kernel(const fp16* __restrict__ pjf,
        const fp16* __restrict__ vbf, const float* __restrict__ wif,
        const float* __restrict__ bif, float* __restrict__ gates){
    __shared__ float As[16*128];
    __shared__ float Ws[128*17];
    int m0 = blockIdx.x*16;
    int tid = threadIdx.x;
    int r = tid >> 4, g = tid & 15;
    float acc = 0.f;
    for (int j0=0; j0<6144; j0+=128){
        __syncthreads();
        for (int e=tid; e<2048; e+=256){
            int jj = e & 127, rr = e >> 7;
            int j = j0 + jj;
            int hh = j/768, t = j - hh*768;
            long m = m0 + rr;
            fp16 v = (t < 512) ? pjf[m*4096 + hh*512 + t]
                               : vbf[m*2048 + hh*256 + (t-512)];
            As[rr*128 + jj] = __half2float(v);
        }
        for (int e=tid; e<2048; e+=256){
            int jj = e & 127, gg = e >> 7;
            Ws[jj*17 + gg] = wif[(long)gg*6144 + j0 + jj];
        }
        __syncthreads();
        #pragma unroll 8
        for (int j=0;j<128;j++) acc += As[r*128 + j]*Ws[j*17 + g];
    }
    gates[(long)(m0+r)*16 + g] = acc + bif[g];
}

// ---------------- per-(b,h) scans ----------------
__global__ __launch_bounds__(512) void scan_kernel(const float* __restrict__ gates,
        float* __restrict__ ga, float* __restrict__ Ma, float* __restrict__ ea){
    int bh = blockIdx.x, b = bh >> 3, h = bh & 7;
    int t = threadIdx.x;
    __shared__ float sd[512];
    long base = (long)b*Lq;
    float ls[3], fc[3];
    #pragma unroll
    for (int u=0;u<3;u++){
        int l = t*3 + u;
        float f = gates[(base + l)*16 + 8 + h];
        ls[u] = (f >= 0.f) ? -log1pf(expf(-f)) : (f - log1pf(expf(f)));
    }
    float tot = ls[0] + ls[1] + ls[2];
    sd[t] = tot;
    __syncthreads();
    for (int off=1; off<512; off<<=1){
        float add = (t >= off) ? sd[t-off] : 0.f;
        __syncthreads();
        sd[t] += add;
        __syncthreads();
    }
    float excl = (t > 0) ? sd[t-1] : 0.f;
    fc[0] = excl + ls[0]; fc[1] = fc[0] + ls[1]; fc[2] = fc[1] + ls[2];
    __syncthreads();
    float gv[3], pm[3];
    #pragma unroll
    for (int u=0;u<3;u++){
        int l = t*3 + u;
        float ig = gates[(base + l)*16 + h];
        gv[u] = expf(ig) - fc[u];
    }
    pm[0] = gv[0]; pm[1] = fmaxf(pm[0], gv[1]); pm[2] = fmaxf(pm[1], gv[2]);
    sd[t] = pm[2];
    __syncthreads();
    for (int off=1; off<512; off<<=1){
        float add = (t >= off) ? sd[t-off] : -3.4e38f;
        __syncthreads();
        sd[t] = fmaxf(sd[t], add);
        __syncthreads();
    }
    float exm = (t > 0) ? sd[t-1] : -3.4e38f;
    #pragma unroll
    for (int u=0;u<3;u++){
        int l = t*3 + u;
        float Ml = fmaxf(exm, pm[u]);
        ga[(long)bh*Lq + l] = gv[u];
        Ma[(long)bh*Lq + l] = Ml;
        ea[(long)bh*Lq + l] = expf(-fc[u] - Ml);
    }
}

// ---------------- tensor-core mLSTM attention: 256 threads, 128 q-rows/CTA ----------------
// smem: Q 128x528B | K0 | K1 | V0 | V1 (each 64x528B) | E[64]
#define Q_OFF  0
#define K0_OFF 67584
#define V0_OFF 135168
#define E_OFF  202752
#define ATT_SMEM 203008

__global__ __launch_bounds__(256, 1) void attn2(
    const fp16* __restrict__ pjf, const fp16* __restrict__ vbf,
    const fp16* __restrict__ qkf, const fp16* __restrict__ yf,
    const float* __restrict__ ga, const float* __restrict__ Ma,
    const float* __restrict__ ea, const float* __restrict__ skip,
    const float* __restrict__ hnw,
    fp16* __restrict__ xmf)
{
    extern __shared__ char sm[];
    const uint32_t smb = smem_u32(sm);
    float* Esm = (float*)(sm + E_OFF);

    int tid = threadIdx.x, w = tid >> 5, lane = tid & 31;
    int bh = blockIdx.y, b = bh >> 3, h = bh & 7;
    int jj = (int)gridDim.x - 1 - (int)blockIdx.x;
    long mbase = (long)b*Lq;
    int o0 = jj*128;
    int ntiles = 2*jj + 2;

    int rowg = w*16 + (lane >> 2);
    float F0  = expf(-Ma[(long)bh*Lq + o0 + rowg])     * 0.0625f;
    float F8  = expf(-Ma[(long)bh*Lq + o0 + rowg + 8]) * 0.0625f;
    float en0 = ea[(long)bh*Lq + o0 + rowg];
    float en8 = ea[(long)bh*Lq + o0 + rowg + 8];

    for (int j = tid; j < 4096; j += 256){
        int row = j >> 5, c = j & 31;
        cp16(smb + Q_OFF + row*528 + c*16, pjf + (mbase + o0 + row)*4096 + h*512 + c*8);
    }
    cp_commit();

    auto issueTile = [&](int it){
        long i0 = (long)it*64;
        uint32_t kb = smb + K0_OFF + (it & 1)*33792;
        uint32_t vb2 = smb + V0_OFF + (it & 1)*33792;
        for (int j = tid; j < 2048; j += 256){
            int row = j >> 5, c = j & 31;
            cp16(kb + row*528 + c*16, pjf + (mbase + i0 + row)*4096 + h*512 + 256 + c*8);
        }
        for (int j = tid; j < 2048; j += 256){
            int row = j >> 5, c = j & 31;
            cp16(vb2 + row*528 + c*16, vbf + (mbase + i0 + row)*2048 + h*256 + c*8);
        }
    };
    issueTile(0); cp_commit();
    issueTile(1); cp_commit();

    float accH[32][4];
    #pragma unroll
    for (int g=0; g<32; g++){ accH[g][0]=0.f; accH[g][1]=0.f; accH[g][2]=0.f; accH[g][3]=0.f; }
    uint32_t pk[8][2];
    float rs0 = 0.f, rs1 = 0.f;

    uint32_t qrow = (uint32_t)((w*16 + (lane & 15))*528 + (lane >> 4)*16);
    int gb = lane >> 3;
    uint32_t krow = (uint32_t)(((((gb >> 1) << 3) + (lane & 7)))*528 + (gb & 1)*16);
    uint32_t vrow = (uint32_t)((lane & 15)*528 + (lane >> 4)*16);

    for (int it = 0; it < ntiles; it++){
        cp_wait1();
        if (tid < 64) Esm[tid] = expf(ga[(long)bh*Lq + (long)it*64 + tid]);
        __syncthreads();

        bool active = (it*64 <= o0 + w*16 + 15);
        if (active){
            uint32_t kb = smb + K0_OFF + (it & 1)*33792;
            uint32_t vb2 = smb + V0_OFF + (it & 1)*33792;

            float sacc[8][4];
            #pragma unroll
            for (int g=0; g<8; g++){ sacc[g][0]=0.f; sacc[g][1]=0.f; sacc[g][2]=0.f; sacc[g][3]=0.f; }
            #pragma unroll
            for (int ks=0; ks<16; ks++){
                uint32_t q4[4];
                ldsm_x4(q4, smb + Q_OFF + qrow + ks*32);
                #pragma unroll
                for (int kt=0; kt<4; kt++){
                    uint32_t b4[4];
                    ldsm_x4(b4, kb + krow + kt*(16*528) + ks*32);
                    mma16816(sacc[kt*2],   q4, b4);
                    mma16816(sacc[kt*2+1], q4, b4 + 2);
                }
            }
            bool needmask = (it*64 + 63 > o0 + w*16);
            int qg0 = o0 + rowg, qg8 = qg0 + 8;
            #pragma unroll
            for (int nt=0; nt<8; nt++){
                int cb = nt*8 + (lane & 3)*2;
                int kg = it*64 + cb;
                float e0 = Esm[cb], e1 = Esm[cb+1];
                float w00 = e0*F0, w01 = e1*F0, w10 = e0*F8, w11 = e1*F8;
                if (needmask){
                    if (kg     > qg0) w00 = 0.f;
                    if (kg + 1 > qg0) w01 = 0.f;
                    if (kg     > qg8) w10 = 0.f;
                    if (kg + 1 > qg8) w11 = 0.f;
                }
                float c0 = sacc[nt][0]*w00, c1 = sacc[nt][1]*w01;
                float c2 = sacc[nt][2]*w10, c3 = sacc[nt][3]*w11;
                rs0 += c0 + c1; rs1 += c2 + c3;
                pk[nt][0] = pack2(__float2half_rn(c0), __float2half_rn(c1));
                pk[nt][1] = pack2(__float2half_rn(c2), __float2half_rn(c3));
            }
            #pragma unroll
            for (int kk=0; kk<4; kk++){
                uint32_t aP[4] = { pk[2*kk][0], pk[2*kk][1], pk[2*kk+1][0], pk[2*kk+1][1] };
                #pragma unroll
                for (int dc=0; dc<16; dc++){
                    uint32_t tH[4];
                    ldsm_x4t(tH, vb2 + vrow + kk*(16*528) + dc*32);
                    mma16816(accH[2*dc],   aP, tH);
                    mma16816(accH[2*dc+1], aP, tH + 2);
                }
            }
        }
        __syncthreads();
        if (it + 2 < ntiles) issueTile(it + 2);
        cp_commit();
    }

    rs0 += __shfl_xor_sync(0xffffffffu, rs0, 1);
    rs0 += __shfl_xor_sync(0xffffffffu, rs0, 2);
    rs1 += __shfl_xor_sync(0xffffffffu, rs1, 1);
    rs1 += __shfl_xor_sync(0xffffffffu, rs1, 2);
    float inv0 = 1.f / fmaxf(fabsf(rs0), en0);
    float inv1 = 1.f / fmaxf(fabsf(rs1), en8);

    float s0=0.f, q0=0.f, s1=0.f, q1=0.f;
    #pragma unroll
    for (int g=0; g<32; g++){
        float v0 = accH[g][0]*inv0, v1 = accH[g][1]*inv0;
        float v2 = accH[g][2]*inv1, v3 = accH[g][3]*inv1;
        accH[g][0]=v0; accH[g][1]=v1; accH[g][2]=v2; accH[g][3]=v3;
        s0 += v0 + v1; q0 += v0*v0 + v1*v1;
        s1 += v2 + v3; q1 += v2*v2 + v3*v3;
    }
    s0 += __shfl_xor_sync(0xffffffffu, s0, 1); s0 += __shfl_xor_sync(0xffffffffu, s0, 2);
    q0 += __shfl_xor_sync(0xffffffffu, q0, 1); q0 += __shfl_xor_sync(0xffffffffu, q0, 2);
    s1 += __shfl_xor_sync(0xffffffffu, s1, 1); s1 += __shfl_xor_sync(0xffffffffu, s1, 2);
    q1 += __shfl_xor_sync(0xffffffffu, q1, 1); q1 += __shfl_xor_sync(0xffffffffu, q1, 2);
    float mu0 = s0*(1.f/256.f), var0 = q0*(1.f/256.f) - mu0*mu0, rst0 = rsqrtf(var0 + 1e-5f);
    float mu1 = s1*(1.f/256.f), var1 = q1*(1.f/256.f) - mu1*mu1, rst1 = rsqrtf(var1 + 1e-5f);

    long mr0 = mbase + o0 + rowg;
    long mr8 = mr0 + 8;
    #pragma unroll
    for (int g=0; g<32; g++){
        int d0 = g*8 + (lane & 3)*2;
        int col = h*256 + d0;
        float2 hw = *(const float2*)(hnw + d0);
        float2 sk = *(const float2*)(skip + col);
        {
            float2 q2 = __half22float2(*(const __half2*)(qkf + mr0*2048 + col));
            float2 x2 = __half22float2(*(const __half2*)(yf + mr0*4096 + 2048 + col));
            float hv0 = (accH[g][0] - mu0)*rst0*hw.x;
            float hv1 = (accH[g][1] - mu0)*rst0*hw.y;
            float a0 = hv0 + sk.x*q2.x, a1 = hv1 + sk.y*q2.y;
            float r0 = a0 * (x2.x / (1.f + expf(-x2.x)));
            float r1 = a1 * (x2.y / (1.f + expf(-x2.y)));
            *(uint32_t*)(xmf + mr0*2048 + col) = pack2(__float2half_rn(r0), __float2half_rn(r1));
        }
        {
            float2 q2 = __half22float2(*(const __half2*)(qkf + mr8*2048 + col));
            float2 x2 = __half22float2(*(const __half2*)(yf + mr8*4096 + 2048 + col));
            float hv0 = (accH[g][2] - mu1)*rst1*hw.x;
            float hv1 = (accH[g][3] - mu1)*rst1*hw.y;
            float a0 = hv0 + sk.x*q2.x, a1 = hv1 + sk.y*q2.y;
            float r0 = a0 * (x2.x / (1.f + expf(-x2.x)));
            float r1 = a1 * (x2.y / (1.f + expf(-x2.y)));
            *(uint32_t*)(xmf + mr8*2048 + col) = pack2(__float2half_rn(r0), __float2half_rn(r1));
        }
    }
}

// ---------------- host ----------------
extern "C" void kernel_launch(void* const* d_in, const int* in_sizes, int n_in,
                              void* d_out, int out_size){
    const float* x      = (const float*)d_in[0];
    const float* ln_w   = (const float*)d_in[1];
    const float* ln_b   = (const float*)d_in[2];
    const float* w1     = (const float*)d_in[3];
    const float* b1     = (const float*)d_in[4];
    const float* conv_w = (const float*)d_in[5];
    const float* conv_b = (const float*)d_in[6];
    const float* skip   = (const float*)d_in[7];
    const float* wqk    = (const float*)d_in[8];
    const float* bqk    = (const float*)d_in[9];
    const float* wv     = (const float*)d_in[10];
    const float* bv     = (const float*)d_in[11];
    const float* wif    = (const float*)d_in[12];
    const float* bif    = (const float*)d_in[13];
    const float* hn_w   = (const float*)d_in[14];
    const float* w2     = (const float*)d_in[15];
    const float* b2     = (const float*)d_in[16];
    float* out = (float*)d_out;

    fp16 *xlnf,*yf,*qkf,*xmf,*pjf,*vbf;
    fp16 *w1f,*cwtf,*wqkTf,*wvTf,*w2f;
    float *gates,*gA,*MA,*eA;
    cudaGetSymbolAddress((void**)&xlnf, d_xlnf);
    cudaGetSymbolAddress((void**)&yf,   d_yf);
    cudaGetSymbolAddress((void**)&qkf,  d_qkf);
    cudaGetSymbolAddress((void**)&pjf,  d_pjf);
    cudaGetSymbolAddress((void**)&vbf,  d_vbf);
    cudaGetSymbolAddress((void**)&xmf,  d_xmf);
    cudaGetSymbolAddress((void**)&gates,d_gates);
    cudaGetSymbolAddress((void**)&gA,   d_g);
    cudaGetSymbolAddress((void**)&MA,   d_M);
    cudaGetSymbolAddress((void**)&eA,   d_enm);
    cudaGetSymbolAddress((void**)&w1f,  d_w1f);
    cudaGetSymbolAddress((void**)&cwtf, d_cwtf);
    cudaGetSymbolAddress((void**)&wqkTf,d_wqkTf);
    cudaGetSymbolAddress((void**)&wvTf, d_wvTf);
    cudaGetSymbolAddress((void**)&w2f,  d_w2f);

    cudaFuncSetAttribute(hgemm<2>, cudaFuncAttributeMaxDynamicSharedMemorySize, 110592);
    cudaFuncSetAttribute(hgemm<1>, cudaFuncAttributeMaxDynamicSharedMemorySize, 82944);
    cudaFuncSetAttribute(attn2, cudaFuncAttributeMaxDynamicSharedMemorySize, ATT_SMEM);

    // order chosen so ncu's captured slot (4th launch) hits hgemm<2> GEMM1
    quant_plain4<<<(int)((4096L*1024/4 + 255)/256), 256>>>((const float4*)w1, (__half2*)w1f, 4096L*1024/4);  // 1
    ln_kernel<<<Mq, 256>>>(x, ln_w, ln_b, xlnf);                                                             // 2
    quant_plain4<<<(int)((1024L*2048/4 + 255)/256), 256>>>((const float4*)w2, (__half2*)w2f, 1024L*2048/4);  // 3

    // 4: yf = fp16(LN(x) @ w1^T + b1), full width
    {
        G5P p = {};
        p.Af = xlnf; p.Bf = w1f;
        p.Cf = 0; p.Oh = yf; p.bias = b1;
        p.K = 1024; p.lda = 1024; p.ldb = 1024; p.ldo = 4096;
        p.epi = 1; p.ntaps = 1; p.splitNmax = 4096;
        hgemm<2><<<dim3(32, 24, 1), 512, 110592>>>(p);
    }

    prep_cwt<<<(int)(((long)Cq*Cq/2 + 255)/256), 256>>>((const float4*)conv_w, (__half2*)cwtf);
    prep_wqkv<<<(Hq*512*256 + Hq*256*256 + 255)/256, 256>>>(wqk, wv, wqkTf, wvTf);

    // qkf = fp16(silu(conv(x1))) — x1 = yf cols [0,2048); heavy blocks first
    {
        G5P p = {};
        p.Af = yf; p.Bf = cwtf;
        p.Cf = 0; p.Oh = qkf; p.bias = conv_b;
        p.K = Cq; p.lda = 4096; p.ldb = Cq; p.ldo = Cq;
        p.epi = 1|2|8; p.splitNmax = Cq;
        p.ntaps  = 1; p.aTap[0]  = 0;              p.bTap[0]  = (long)3*Cq*Cq;
        p.ntaps2 = 2; p.aTap2[0] = 0;              p.bTap2[0] = (long)2*Cq*Cq;
                      p.aTap2[1] = (long)Lq*4096;  p.bTap2[1] = (long)3*Cq*Cq;
        hgemm<2><<<dim3(16, 24, 1), 512, 110592>>>(p);
    }

    // per-head proj = qk_h @ wqk_h + bqk  (fp16 only)
    {
        G5P p = {};
        p.Af = qkf; p.Bf = wqkTf;
        p.Cf = 0; p.Oh = pjf; p.bias = bqk;
        p.K = 256; p.lda = 2048; p.ldb = 256; p.ldo = 4096;
        p.aZ = 256; p.bZ = (long)512*256; p.biasZ = 512; p.oZ = 512;
        p.epi = 1; p.ntaps = 1; p.splitNmax = 512;
        hgemm<2><<<dim3(4, 24, Hq), 512, 110592>>>(p);
    }
    // per-head v = x1_h @ wv_h + bv  (fp16 only; x1 = yf cols [0,2048))
    {
        G5P p = {};
        p.Af = yf; p.Bf = wvTf;
        p.Cf = 0; p.Oh = vbf; p.bias = bv;
        p.K = 256; p.lda = 4096; p.ldb = 256; p.ldo = 2048;
        p.aZ = 256; p.bZ = (long)256*256; p.biasZ = 256; p.oZ = 256;
        p.epi = 1; p.ntaps = 1; p.splitNmax = 256;
        hgemm<2><<<dim3(2, 24, Hq), 512, 110592>>>(p);
    }

    gates_kernel<<<Mq/16, 256>>>(pjf, vbf, wif, bif, gates);
    scan_kernel<<<Bq*Hq, 512>>>(gates, gA, MA, eA);

    attn2<<<dim3(12, 16), 256, ATT_SMEM>>>(pjf, vbf, qkf, yf,
                                           gA, MA, eA, skip, hn_w, xmf);

    // out = xm @ w2^T + b2 + x
    {
        G5P p = {};
        p.Af = xmf; p.Bf = w2f;
        p.Cf = out; p.bias = b2; p.add = x;
        p.K = Cq; p.lda = 2048; p.ldb = 2048; p.ldc = 1024; p.ldadd = 1024;
        p.epi = 1|4; p.ntaps = 1; p.splitNmax = 0; p.cfMin = 0;
        hgemm<1><<<dim3(8, 48, 1), 512, 82944>>>(p);
    }
}

// round 17
// speedup vs baseline: 1.1574x; 1.0087x over previous
#include <cuda_runtime.h>
#include <cuda_fp16.h>
#include <math.h>
#include <stdint.h>

#define Bq 2
#define Lq 1536
#define Dq 1024
#define Hq 8
#define Cq 2048
#define DPHq 256
#define Mq (Bq*Lq)   /* 3072 */

typedef __half fp16;

// ---------------- scratch (static device globals; no allocation) ----------------
__device__ __align__(128) fp16  d_xlnf[(size_t)Mq*Dq];
__device__ __align__(128) fp16  d_yf[(size_t)Mq*4096];     // [x1 | x2] fp16
__device__ __align__(128) fp16  d_qkf[(size_t)Mq*Cq];
__device__ __align__(128) fp16  d_pjf[(size_t)Mq*4096];
__device__ __align__(128) fp16  d_vbf[(size_t)Mq*Cq];
__device__ __align__(128) fp16  d_xmf[(size_t)Mq*Cq];
__device__ float d_gates[(size_t)Mq*16];
__device__ float d_g[16*Lq];
__device__ float d_M[16*Lq];
__device__ float d_enm[16*Lq];
__device__ __align__(128) fp16  d_w1f[4096*1024];
__device__ __align__(128) fp16  d_cwtf[(size_t)4*Cq*Cq];
__device__ __align__(128) fp16  d_wqkTf[Hq*512*256];
__device__ __align__(128) fp16  d_wvTf[Hq*256*256];
__device__ __align__(128) fp16  d_w2f[1024*2048];

// ---------------- helpers ----------------
__device__ __forceinline__ uint32_t smem_u32(const void* p){
    return (uint32_t)__cvta_generic_to_shared(p);
}
__device__ __forceinline__ void cp16(uint32_t dst, const void* src){
    asm volatile("cp.async.cg.shared.global [%0], [%1], 16;" :: "r"(dst), "l"(src));
}
__device__ __forceinline__ void cp_commit(){ asm volatile("cp.async.commit_group;" ::: "memory"); }
__device__ __forceinline__ void cp_wait0(){ asm volatile("cp.async.wait_group 0;" ::: "memory"); }
__device__ __forceinline__ void cp_wait1(){ asm volatile("cp.async.wait_group 1;" ::: "memory"); }
__device__ __forceinline__ void cp_wait2(){ asm volatile("cp.async.wait_group 2;" ::: "memory"); }

__device__ __forceinline__ void ldsm_x4(uint32_t* r, uint32_t addr){
    asm volatile("ldmatrix.sync.aligned.m8n8.x4.shared.b16 {%0,%1,%2,%3}, [%4];"
                 : "=r"(r[0]), "=r"(r[1]), "=r"(r[2]), "=r"(r[3]) : "r"(addr));
}
__device__ __forceinline__ void ldsm_x4t(uint32_t* r, uint32_t addr){
    asm volatile("ldmatrix.sync.aligned.m8n8.x4.trans.shared.b16 {%0,%1,%2,%3}, [%4];"
                 : "=r"(r[0]), "=r"(r[1]), "=r"(r[2]), "=r"(r[3]) : "r"(addr));
}
__device__ __forceinline__ void mma16816(float* d, const uint32_t* a, const uint32_t* b){
    asm volatile(
        "mma.sync.aligned.m16n8k16.row.col.f32.f16.f16.f32 "
        "{%0,%1,%2,%3}, {%4,%5,%6,%7}, {%8,%9}, {%0,%1,%2,%3};"
        : "+f"(d[0]), "+f"(d[1]), "+f"(d[2]), "+f"(d[3])
        : "r"(a[0]), "r"(a[1]), "r"(a[2]), "r"(a[3]), "r"(b[0]), "r"(b[1]));
}
__device__ __forceinline__ uint32_t pack2(fp16 a, fp16 b){
    uint16_t ua = *(uint16_t*)&a, ub = *(uint16_t*)&b;
    return (uint32_t)ua | ((uint32_t)ub << 16);
}

// ---------------- fused prep kernels ----------------
// prep_main: blocks [0,4096) quant w1; blocks [4096,7168) LN(x)
__global__ __launch_bounds__(256) void prep_main(
        const float4* __restrict__ w1, __half2* __restrict__ w1f,
        const float* __restrict__ x, const float* __restrict__ lnw,
        const float* __restrict__ lnb, fp16* __restrict__ xlnf){
    __shared__ float s1[256], s2[256];
    int bx = blockIdx.x, t = threadIdx.x;
    if (bx < 4096){
        long i = (long)bx*256 + t;          // n4 = 1048576
        float4 v = w1[i];
        w1f[2*i]   = __floats2half2_rn(v.x, v.y);
        w1f[2*i+1] = __floats2half2_rn(v.z, v.w);
    } else {
        int m = bx - 4096;
        float v[4]; float s = 0.f, q = 0.f;
        #pragma unroll
        for (int u=0;u<4;u++){ v[u] = x[(long)m*Dq + t + u*256]; s += v[u]; q += v[u]*v[u]; }
        s1[t] = s; s2[t] = q; __syncthreads();
        for (int off=128; off; off>>=1){
            if (t < off){ s1[t] += s1[t+off]; s2[t] += s2[t+off]; }
            __syncthreads();
        }
        float mu = s1[0]*(1.f/1024.f);
        float var = s2[0]*(1.f/1024.f) - mu*mu;
        float rs = rsqrtf(var + 1e-5f);
        #pragma unroll
        for (int u=0;u<4;u++){
            int c = t + u*256;
            xlnf[(long)m*Dq + c] = __float2half_rn((v[u]-mu)*rs*lnw[c] + lnb[c]);
        }
    }
}

// prep_rest: [0,2048) quant w2 ; [2048,10240) conv_w transpose ; [10240,16384) wqk/wv
__global__ __launch_bounds__(256) void prep_rest(
        const float4* __restrict__ w2, __half2* __restrict__ w2f,
        const float4* __restrict__ cw, __half2* __restrict__ cwtf,
        const float* __restrict__ wqk, const float* __restrict__ wv,
        fp16* __restrict__ qf, fp16* __restrict__ vf){
    int bx = blockIdx.x, t = threadIdx.x;
    if (bx < 2048){
        long i = (long)bx*256 + t;          // n4 = 524288
        float4 v = w2[i];
        w2f[2*i]   = __floats2half2_rn(v.x, v.y);
        w2f[2*i+1] = __floats2half2_rn(v.z, v.w);
    } else if (bx < 10240){
        const long NP = (long)Cq*Cq/2;      // 2097152 -> 8192 blocks
        long i = (long)(bx - 2048)*256 + t;
        float4 a = cw[2*i], b = cw[2*i+1];
        cwtf[i]        = __floats2half2_rn(a.x, b.x);
        cwtf[NP + i]   = __floats2half2_rn(a.y, b.y);
        cwtf[2*NP + i] = __floats2half2_rn(a.z, b.z);
        cwtf[3*NP + i] = __floats2half2_rn(a.w, b.w);
    } else {
        int idx = (bx - 10240)*256 + t;     // 6144 blocks
        if (idx < Hq*512*256){
            int hh = idx/(512*256); int r = idx%(512*256); int o = r/256; int i = r%256;
            qf[idx] = __float2half_rn(wqk[hh*131072 + i*512 + o]);
        } else {
            int j = idx - Hq*512*256;
            if (j < Hq*256*256){
                int hh = j/65536; int r = j%65536; int o = r/256; int i = r%256;
                vf[j] = __float2half_rn(wv[hh*65536 + i*256 + o]);
            }
        }
    }
}

// ---------------- fp16 mma.sync GEMM (512 threads, BK=64): C = A @ B^T ----------------
// epi bits: 1=bias, 2=silu, 4=residual add, 8=conv mode (batch taps + heavy-first y)
struct G5P {
    const fp16 *Af, *Bf;
    float* Cf;
    fp16 *Oh;
    const float* bias; const float* add;
    int K, lda, ldb, ldc, ldo, ldadd, epi, ntaps, ntaps2, splitNmax, cfMin;
    long aZ, bZ, cZ, biasZ, oZ;
    long aTap[2], bTap[2];
    long aTap2[2], bTap2[2];
};

template<int MT>
__global__ __launch_bounds__(512, 1) void hgemm(G5P p){
    constexpr int BM = MT*64;
    constexpr int TA = BM*144;
    constexpr int TB = 128*144;
    constexpr int STG = TA + TB;
    extern __shared__ char sm[];
    int tid = threadIdx.x;
    int warp = tid >> 5, lane = tid & 31;
    int wm = warp >> 2, wn = warp & 3;

    long byy = (p.epi & 8) ? (long)(gridDim.y - 1 - blockIdx.y) : (long)blockIdx.y;
    long m0 = byy*BM;
    int  n0 = blockIdx.x*128;

    long arow; int ntaps; long aT[2], bT[2];
    if (p.epi & 8){
        int batch = (int)(m0 / Lq);
        arow = m0 - (long)batch*Lq;
        if (batch == 0){ ntaps = p.ntaps;  aT[0]=p.aTap[0];  bT[0]=p.bTap[0];  aT[1]=p.aTap[1];  bT[1]=p.bTap[1]; }
        else           { ntaps = p.ntaps2; aT[0]=p.aTap2[0]; bT[0]=p.bTap2[0]; aT[1]=p.aTap2[1]; bT[1]=p.bTap2[1]; }
    } else {
        arow = m0; ntaps = p.ntaps;
        aT[0]=p.aTap[0]; bT[0]=p.bTap[0]; aT[1]=p.aTap[1]; bT[1]=p.bTap[1];
    }

    long aoff = (long)blockIdx.z*p.aZ + arow*p.lda;
    long boff = (long)blockIdx.z*p.bZ + (long)n0*p.ldb;
    int cpt = p.K >> 6;
    int nch = ntaps * cpt;

    uint32_t smb = smem_u32(sm);
    float acc[MT][4][4] = {};

    auto loadChunk = [&](int c){
        int tap = c / cpt;
        int k0  = (c - tap*cpt) << 6;
        uint32_t stg = smb + (c % 3)*STG;
        const fp16* baseA = p.Af + aoff + aT[tap] + k0;
        #pragma unroll
        for (int j = tid; j < BM*8; j += 512){
            int row = j >> 3, ch = j & 7;
            cp16(stg + row*144 + ch*16, baseA + (long)row*p.lda + ch*8);
        }
        const fp16* baseB = p.Bf + boff + bT[tap] + k0;
        #pragma unroll
        for (int j = tid; j < 1024; j += 512){
            int row = j >> 3, ch = j & 7;
            cp16(stg + TA + row*144 + ch*16, baseB + (long)row*p.ldb + ch*8);
        }
    };

    loadChunk(0); cp_commit();
    if (nch > 1){ loadChunk(1); cp_commit(); }

    for (int c=0; c<nch; c++){
        if (c+2 < nch){ loadChunk(c+2); cp_commit(); cp_wait2(); }
        else if (c+1 < nch){ cp_wait1(); }
        else { cp_wait0(); }
        __syncthreads();

        uint32_t stg = smb + (c % 3)*STG;
        uint32_t aB_ = stg, bB = stg + TA;

        int lr = lane & 15, lcs = lane >> 4;
        int gb = lane >> 3, bnr = lane & 7;
        int rowA = wm*(MT*16) + lr;
        int rowB = wn*32 + ((gb >> 1) << 3) + bnr;

        #pragma unroll
        for (int ks=0; ks<4; ks++){
            uint32_t af[MT][4], bf[4][2];
            uint32_t aoffb = (uint32_t)((rowA*9 + ks*2 + lcs) * 16);
            #pragma unroll
            for (int mt=0; mt<MT; mt++)
                ldsm_x4(af[mt], aB_ + aoffb + mt*2304);
            uint32_t boffb = (uint32_t)((rowB*9 + ks*2 + (gb & 1)) * 16);
            uint32_t t4[4];
            #pragma unroll
            for (int np=0; np<2; np++){
                ldsm_x4(t4, bB + boffb + np*2304);
                bf[np*2][0]=t4[0]; bf[np*2][1]=t4[1]; bf[np*2+1][0]=t4[2]; bf[np*2+1][1]=t4[3];
            }
            #pragma unroll
            for (int mt=0; mt<MT; mt++)
                #pragma unroll
                for (int nt=0; nt<4; nt++)
                    mma16816(acc[mt][nt], af[mt], bf[nt]);
        }
        __syncthreads();
    }

    float* eps = (float*)sm;
    #pragma unroll
    for (int mt=0; mt<MT; mt++){
        int r0 = wm*(MT*16) + mt*16 + (lane >> 2);
        #pragma unroll
        for (int nt=0; nt<4; nt++){
            int c0 = wn*32 + nt*8 + (lane & 3)*2;
            eps[r0*132 + c0]       = acc[mt][nt][0];
            eps[r0*132 + c0 + 1]   = acc[mt][nt][1];
            eps[(r0+8)*132 + c0]   = acc[mt][nt][2];
            eps[(r0+8)*132 + c0+1] = acc[mt][nt][3];
        }
    }
    __syncthreads();

    const float* bias = p.bias ? (p.bias + (long)blockIdx.z*p.biasZ) : (const float*)0;
    long czo = (long)blockIdx.z * p.cZ;
    long ozo = (long)blockIdx.z * p.oZ;
    for (int j = tid; j < BM*128; j += 512){
        int rr = j >> 7, cc = j & 127;
        long m = m0 + rr;
        int n = n0 + cc;
        float val = eps[rr*132 + cc];
        if (bias) val += bias[n];
        if (p.epi & 2){ val = val / (1.f + expf(-val)); }
        if (p.epi & 4){ val += p.add[m*p.ldadd + n]; }
        if (p.Cf && n >= p.cfMin) p.Cf[m*p.ldc + czo + n] = val;
        if (n < p.splitNmax)
            p.Oh[m*p.ldo + ozo + n] = __float2half_rn(val);
    }
}

// ---------------- gates (R12-proven: 16 rows/block, 256 threads) ----------------
__global__ __launch_bounds__(256) void gates_kernel(const fp16* __restrict__ pjf,
        const fp16* __restrict__ vbf, const float* __restrict__ wif,
        const float* __restrict__ bif, float* __restrict__ gates){
    __shared__ float As[16*128];
    __shared__ float Ws[128*17];
    int m0 = blockIdx.x*16;
    int tid = threadIdx.x;
    int r = tid >> 4, g = tid & 15;
    float acc = 0.f;
    for (int j0=0; j0<6144; j0+=128){
        __syncthreads();
        for (int e=tid; e<2048; e+=256){
            int jj = e & 127, rr = e >> 7;
            int j = j0 + jj;
            int hh = j/768, t = j - hh*768;
            long m = m0 + rr;
            fp16 v = (t < 512) ? pjf[m*4096 + hh*512 + t]
                               : vbf[m*2048 + hh*256 + (t-512)];
            As[rr*128 + jj] = __half2float(v);
        }
        for (int e=tid; e<2048; e+=256){
            int jj = e & 127, gg = e >> 7;
            Ws[jj*17 + gg] = wif[(long)gg*6144 + j0 + jj];
        }
        __syncthreads();
        #pragma unroll 8
        for (int j=0;j<128;j++) acc += As[r*128 + j]*Ws[j*17 + g];
    }
    gates[(long)(m0+r)*16 + g] = acc + bif[g];
}

// ---------------- per-(b,h) scans ----------------
__global__ __launch_bounds__(512) void scan_kernel(const float* __restrict__ gates,
        float* __restrict__ ga, float* __restrict__ Ma, float* __restrict__ ea){
    int bh = blockIdx.x, b = bh >> 3, h = bh & 7;
    int t = threadIdx.x;
    __shared__ float sd[512];
    long base = (long)b*Lq;
    float ls[3], fc[3];
    #pragma unroll
    for (int u=0;u<3;u++){
        int l = t*3 + u;
        float f = gates[(base + l)*16 + 8 + h];
        ls[u] = (f >= 0.f) ? -log1pf(expf(-f)) : (f - log1pf(expf(f)));
    }
    float tot = ls[0] + ls[1] + ls[2];
    sd[t] = tot;
    __syncthreads();
    for (int off=1; off<512; off<<=1){
        float add = (t >= off) ? sd[t-off] : 0.f;
        __syncthreads();
        sd[t] += add;
        __syncthreads();
    }
    float excl = (t > 0) ? sd[t-1] : 0.f;
    fc[0] = excl + ls[0]; fc[1] = fc[0] + ls[1]; fc[2] = fc[1] + ls[2];
    __syncthreads();
    float gv[3], pm[3];
    #pragma unroll
    for (int u=0;u<3;u++){
        int l = t*3 + u;
        float ig = gates[(base + l)*16 + h];
        gv[u] = expf(ig) - fc[u];
    }
    pm[0] = gv[0]; pm[1] = fmaxf(pm[0], gv[1]); pm[2] = fmaxf(pm[1], gv[2]);
    sd[t] = pm[2];
    __syncthreads();
    for (int off=1; off<512; off<<=1){
        float add = (t >= off) ? sd[t-off] : -3.4e38f;
        __syncthreads();
        sd[t] = fmaxf(sd[t], add);
        __syncthreads();
    }
    float exm = (t > 0) ? sd[t-1] : -3.4e38f;
    #pragma unroll
    for (int u=0;u<3;u++){
        int l = t*3 + u;
        float Ml = fmaxf(exm, pm[u]);
        ga[(long)bh*Lq + l] = gv[u];
        Ma[(long)bh*Lq + l] = Ml;
        ea[(long)bh*Lq + l] = expf(-fc[u] - Ml);
    }
}

// ---------------- tensor-core mLSTM attention: 256 threads, 128 q-rows/CTA ----------------
// smem: Q 128x528B | K0 | K1 | V0 | V1 (each 64x528B) | E[64]
#define Q_OFF  0
#define K0_OFF 67584
#define V0_OFF 135168
#define E_OFF  202752
#define ATT_SMEM 203008

__global__ __launch_bounds__(256, 1) void attn2(
    const fp16* __restrict__ pjf, const fp16* __restrict__ vbf,
    const fp16* __restrict__ qkf, const fp16* __restrict__ yf,
    const float* __restrict__ ga, const float* __restrict__ Ma,
    const float* __restrict__ ea, const float* __restrict__ skip,
    const float* __restrict__ hnw,
    fp16* __restrict__ xmf)
{
    extern __shared__ char sm[];
    const uint32_t smb = smem_u32(sm);
    float* Esm = (float*)(sm + E_OFF);

    int tid = threadIdx.x, w = tid >> 5, lane = tid & 31;
    int bh = blockIdx.y, b = bh >> 3, h = bh & 7;
    int jj = (int)gridDim.x - 1 - (int)blockIdx.x;
    long mbase = (long)b*Lq;
    int o0 = jj*128;
    int ntiles = 2*jj + 2;

    int rowg = w*16 + (lane >> 2);
    float F0  = expf(-Ma[(long)bh*Lq + o0 + rowg])     * 0.0625f;
    float F8  = expf(-Ma[(long)bh*Lq + o0 + rowg + 8]) * 0.0625f;
    float en0 = ea[(long)bh*Lq + o0 + rowg];
    float en8 = ea[(long)bh*Lq + o0 + rowg + 8];

    for (int j = tid; j < 4096; j += 256){
        int row = j >> 5, c = j & 31;
        cp16(smb + Q_OFF + row*528 + c*16, pjf + (mbase + o0 + row)*4096 + h*512 + c*8);
    }
    cp_commit();

    auto issueTile = [&](int it){
        long i0 = (long)it*64;
        uint32_t kb = smb + K0_OFF + (it & 1)*33792;
        uint32_t vb2 = smb + V0_OFF + (it & 1)*33792;
        for (int j = tid; j < 2048; j += 256){
            int row = j >> 5, c = j & 31;
            cp16(kb + row*528 + c*16, pjf + (mbase + i0 + row)*4096 + h*512 + 256 + c*8);
        }
        for (int j = tid; j < 2048; j += 256){
            int row = j >> 5, c = j & 31;
            cp16(vb2 + row*528 + c*16, vbf + (mbase + i0 + row)*2048 + h*256 + c*8);
        }
    };
    issueTile(0); cp_commit();
    issueTile(1); cp_commit();

    float accH[32][4];
    #pragma unroll
    for (int g=0; g<32; g++){ accH[g][0]=0.f; accH[g][1]=0.f; accH[g][2]=0.f; accH[g][3]=0.f; }
    uint32_t pk[8][2];
    float rs0 = 0.f, rs1 = 0.f;

    uint32_t qrow = (uint32_t)((w*16 + (lane & 15))*528 + (lane >> 4)*16);
    int gb = lane >> 3;
    uint32_t krow = (uint32_t)(((((gb >> 1) << 3) + (lane & 7)))*528 + (gb & 1)*16);
    uint32_t vrow = (uint32_t)((lane & 15)*528 + (lane >> 4)*16);

    for (int it = 0; it < ntiles; it++){
        cp_wait1();
        if (tid < 64) Esm[tid] = expf(ga[(long)bh*Lq + (long)it*64 + tid]);
        __syncthreads();

        bool active = (it*64 <= o0 + w*16 + 15);
        if (active){
            uint32_t kb = smb + K0_OFF + (it & 1)*33792;
            uint32_t vb2 = smb + V0_OFF + (it & 1)*33792;

            float sacc[8][4];
            #pragma unroll
            for (int g=0; g<8; g++){ sacc[g][0]=0.f; sacc[g][1]=0.f; sacc[g][2]=0.f; sacc[g][3]=0.f; }
            #pragma unroll
            for (int ks=0; ks<16; ks++){
                uint32_t q4[4];
                ldsm_x4(q4, smb + Q_OFF + qrow + ks*32);
                #pragma unroll
                for (int kt=0; kt<4; kt++){
                    uint32_t b4[4];
                    ldsm_x4(b4, kb + krow + kt*(16*528) + ks*32);
                    mma16816(sacc[kt*2],   q4, b4);
                    mma16816(sacc[kt*2+1], q4, b4 + 2);
                }
            }
            bool needmask = (it*64 + 63 > o0 + w*16);
            int qg0 = o0 + rowg, qg8 = qg0 + 8;
            #pragma unroll
            for (int nt=0; nt<8; nt++){
                int cb = nt*8 + (lane & 3)*2;
                int kg = it*64 + cb;
                float e0 = Esm[cb], e1 = Esm[cb+1];
                float w00 = e0*F0, w01 = e1*F0, w10 = e0*F8, w11 = e1*F8;
                if (needmask){
                    if (kg     > qg0) w00 = 0.f;
                    if (kg + 1 > qg0) w01 = 0.f;
                    if (kg     > qg8) w10 = 0.f;
                    if (kg + 1 > qg8) w11 = 0.f;
                }
                float c0 = sacc[nt][0]*w00, c1 = sacc[nt][1]*w01;
                float c2 = sacc[nt][2]*w10, c3 = sacc[nt][3]*w11;
                rs0 += c0 + c1; rs1 += c2 + c3;
                pk[nt][0] = pack2(__float2half_rn(c0), __float2half_rn(c1));
                pk[nt][1] = pack2(__float2half_rn(c2), __float2half_rn(c3));
            }
            #pragma unroll
            for (int kk=0; kk<4; kk++){
                uint32_t aP[4] = { pk[2*kk][0], pk[2*kk][1], pk[2*kk+1][0], pk[2*kk+1][1] };
                #pragma unroll
                for (int dc=0; dc<16; dc++){
                    uint32_t tH[4];
                    ldsm_x4t(tH, vb2 + vrow + kk*(16*528) + dc*32);
                    mma16816(accH[2*dc],   aP, tH);
                    mma16816(accH[2*dc+1], aP, tH + 2);
                }
            }
        }
        __syncthreads();
        if (it + 2 < ntiles) issueTile(it + 2);
        cp_commit();
    }

    rs0 += __shfl_xor_sync(0xffffffffu, rs0, 1);
    rs0 += __shfl_xor_sync(0xffffffffu, rs0, 2);
    rs1 += __shfl_xor_sync(0xffffffffu, rs1, 1);
    rs1 += __shfl_xor_sync(0xffffffffu, rs1, 2);
    float inv0 = 1.f / fmaxf(fabsf(rs0), en0);
    float inv1 = 1.f / fmaxf(fabsf(rs1), en8);

    float s0=0.f, q0=0.f, s1=0.f, q1=0.f;
    #pragma unroll
    for (int g=0; g<32; g++){
        float v0 = accH[g][0]*inv0, v1 = accH[g][1]*inv0;
        float v2 = accH[g][2]*inv1, v3 = accH[g][3]*inv1;
        accH[g][0]=v0; accH[g][1]=v1; accH[g][2]=v2; accH[g][3]=v3;
        s0 += v0 + v1; q0 += v0*v0 + v1*v1;
        s1 += v2 + v3; q1 += v2*v2 + v3*v3;
    }
    s0 += __shfl_xor_sync(0xffffffffu, s0, 1); s0 += __shfl_xor_sync(0xffffffffu, s0, 2);
    q0 += __shfl_xor_sync(0xffffffffu, q0, 1); q0 += __shfl_xor_sync(0xffffffffu, q0, 2);
    s1 += __shfl_xor_sync(0xffffffffu, s1, 1); s1 += __shfl_xor_sync(0xffffffffu, s1, 2);
    q1 += __shfl_xor_sync(0xffffffffu, q1, 1); q1 += __shfl_xor_sync(0xffffffffu, q1, 2);
    float mu0 = s0*(1.f/256.f), var0 = q0*(1.f/256.f) - mu0*mu0, rst0 = rsqrtf(var0 + 1e-5f);
    float mu1 = s1*(1.f/256.f), var1 = q1*(1.f/256.f) - mu1*mu1, rst1 = rsqrtf(var1 + 1e-5f);

    long mr0 = mbase + o0 + rowg;
    long mr8 = mr0 + 8;
    #pragma unroll
    for (int g=0; g<32; g++){
        int d0 = g*8 + (lane & 3)*2;
        int col = h*256 + d0;
        float2 hw = *(const float2*)(hnw + d0);
        float2 sk = *(const float2*)(skip + col);
        {
            float2 q2 = __half22float2(*(const __half2*)(qkf + mr0*2048 + col));
            float2 x2 = __half22float2(*(const __half2*)(yf + mr0*4096 + 2048 + col));
            float hv0 = (accH[g][0] - mu0)*rst0*hw.x;
            float hv1 = (accH[g][1] - mu0)*rst0*hw.y;
            float a0 = hv0 + sk.x*q2.x, a1 = hv1 + sk.y*q2.y;
            float r0 = a0 * (x2.x / (1.f + expf(-x2.x)));
            float r1 = a1 * (x2.y / (1.f + expf(-x2.y)));
            *(uint32_t*)(xmf + mr0*2048 + col) = pack2(__float2half_rn(r0), __float2half_rn(r1));
        }
        {
            float2 q2 = __half22float2(*(const __half2*)(qkf + mr8*2048 + col));
            float2 x2 = __half22float2(*(const __half2*)(yf + mr8*4096 + 2048 + col));
            float hv0 = (accH[g][2] - mu1)*rst1*hw.x;
            float hv1 = (accH[g][3] - mu1)*rst1*hw.y;
            float a0 = hv0 + sk.x*q2.x, a1 = hv1 + sk.y*q2.y;
            float r0 = a0 * (x2.x / (1.f + expf(-x2.x)));
            float r1 = a1 * (x2.y / (1.f + expf(-x2.y)));
            *(uint32_t*)(xmf + mr8*2048 + col) = pack2(__float2half_rn(r0), __float2half_rn(r1));
        }
    }
}

// ---------------- host ----------------
extern "C" void kernel_launch(void* const* d_in, const int* in_sizes, int n_in,
                              void* d_out, int out_size){
    const float* x      = (const float*)d_in[0];
    const float* ln_w   = (const float*)d_in[1];
    const float* ln_b   = (const float*)d_in[2];
    const float* w1     = (const float*)d_in[3];
    const float* b1     = (const float*)d_in[4];
    const float* conv_w = (const float*)d_in[5];
    const float* conv_b = (const float*)d_in[6];
    const float* skip   = (const float*)d_in[7];
    const float* wqk    = (const float*)d_in[8];
    const float* bqk    = (const float*)d_in[9];
    const float* wv     = (const float*)d_in[10];
    const float* bv     = (const float*)d_in[11];
    const float* wif    = (const float*)d_in[12];
    const float* bif    = (const float*)d_in[13];
    const float* hn_w   = (const float*)d_in[14];
    const float* w2     = (const float*)d_in[15];
    const float* b2     = (const float*)d_in[16];
    float* out = (float*)d_out;

    fp16 *xlnf,*yf,*qkf,*xmf,*pjf,*vbf;
    fp16 *w1f,*cwtf,*wqkTf,*wvTf,*w2f;
    float *gates,*gA,*MA,*eA;
    cudaGetSymbolAddress((void**)&xlnf, d_xlnf);
    cudaGetSymbolAddress((void**)&yf,   d_yf);
    cudaGetSymbolAddress((void**)&qkf,  d_qkf);
    cudaGetSymbolAddress((void**)&pjf,  d_pjf);
    cudaGetSymbolAddress((void**)&vbf,  d_vbf);
    cudaGetSymbolAddress((void**)&xmf,  d_xmf);
    cudaGetSymbolAddress((void**)&gates,d_gates);
    cudaGetSymbolAddress((void**)&gA,   d_g);
    cudaGetSymbolAddress((void**)&MA,   d_M);
    cudaGetSymbolAddress((void**)&eA,   d_enm);
    cudaGetSymbolAddress((void**)&w1f,  d_w1f);
    cudaGetSymbolAddress((void**)&cwtf, d_cwtf);
    cudaGetSymbolAddress((void**)&wqkTf,d_wqkTf);
    cudaGetSymbolAddress((void**)&wvTf, d_wvTf);
    cudaGetSymbolAddress((void**)&w2f,  d_w2f);

    cudaFuncSetAttribute(hgemm<2>, cudaFuncAttributeMaxDynamicSharedMemorySize, 110592);
    cudaFuncSetAttribute(hgemm<1>, cudaFuncAttributeMaxDynamicSharedMemorySize, 82944);
    cudaFuncSetAttribute(attn2, cudaFuncAttributeMaxDynamicSharedMemorySize, ATT_SMEM);

    // lazy-once side stream + events (host objects, reused; identical work per call)
    static cudaStream_t s2 = 0;
    static cudaEvent_t evFork = 0, evJoin = 0;
    if (!s2){
        cudaStreamCreateWithFlags(&s2, cudaStreamNonBlocking);
        cudaEventCreateWithFlags(&evFork, cudaEventDisableTiming);
        cudaEventCreateWithFlags(&evJoin, cudaEventDisableTiming);
    }

    // fork: side stream runs weight prep not needed by GEMM1, overlapping GEMM1
    cudaEventRecord(evFork, 0);
    cudaStreamWaitEvent(s2, evFork, 0);
    prep_rest<<<16384, 256, 0, s2>>>((const float4*)w2, (__half2*)w2f,
                                     (const float4*)conv_w, (__half2*)cwtf,
                                     wqk, wv, wqkTf, wvTf);
    cudaEventRecord(evJoin, s2);

    // main stream: quant w1 + LN fused, then GEMM1
    prep_main<<<7168, 256>>>((const float4*)w1, (__half2*)w1f, x, ln_w, ln_b, xlnf);

    // yf = fp16(LN(x) @ w1^T + b1), full width
    {
        G5P p = {};
        p.Af = xlnf; p.Bf = w1f;
        p.Cf = 0; p.Oh = yf; p.bias = b1;
        p.K = 1024; p.lda = 1024; p.ldb = 1024; p.ldo = 4096;
        p.epi = 1; p.ntaps = 1; p.splitNmax = 4096;
        hgemm<2><<<dim3(32, 24, 1), 512, 110592>>>(p);
    }

    // join: conv needs cwtf; proj needs wqkT; out needs w2f
    cudaStreamWaitEvent(0, evJoin, 0);

    // qkf = fp16(silu(conv(x1))) — x1 = yf cols [0,2048); heavy blocks first
    {
        G5P p = {};
        p.Af = yf; p.Bf = cwtf;
        p.Cf = 0; p.Oh = qkf; p.bias = conv_b;
        p.K = Cq; p.lda = 4096; p.ldb = Cq; p.ldo = Cq;
        p.epi = 1|2|8; p.splitNmax = Cq;
        p.ntaps  = 1; p.aTap[0]  = 0;              p.bTap[0]  = (long)3*Cq*Cq;
        p.ntaps2 = 2; p.aTap2[0] = 0;              p.bTap2[0] = (long)2*Cq*Cq;
                      p.aTap2[1] = (long)Lq*4096;  p.bTap2[1] = (long)3*Cq*Cq;
        hgemm<2><<<dim3(16, 24, 1), 512, 110592>>>(p);
    }

    // per-head proj = qk_h @ wqk_h + bqk  (fp16 only)
    {
        G5P p = {};
        p.Af = qkf; p.Bf = wqkTf;
        p.Cf = 0; p.Oh = pjf; p.bias = bqk;
        p.K = 256; p.lda = 2048; p.ldb = 256; p.ldo = 4096;
        p.aZ = 256; p.bZ = (long)512*256; p.biasZ = 512; p.oZ = 512;
        p.epi = 1; p.ntaps = 1; p.splitNmax = 512;
        hgemm<2><<<dim3(4, 24, Hq), 512, 110592>>>(p);
    }
    // per-head v = x1_h @ wv_h + bv  (fp16 only; x1 = yf cols [0,2048))
    {
        G5P p = {};
        p.Af = yf; p.Bf = wvTf;
        p.Cf = 0; p.Oh = vbf; p.bias = bv;
        p.K = 256; p.lda = 4096; p.ldb = 256; p.ldo = 2048;
        p.aZ = 256; p.bZ = (long)256*256; p.biasZ = 256; p.oZ = 256;
        p.epi = 1; p.ntaps = 1; p.splitNmax = 256;
        hgemm<2><<<dim3(2, 24, Hq), 512, 110592>>>(p);
    }

    gates_kernel<<<Mq/16, 256>>>(pjf, vbf, wif, bif, gates);
    scan_kernel<<<Bq*Hq, 512>>>(gates, gA, MA, eA);

    attn2<<<dim3(12, 16), 256, ATT_SMEM>>>(pjf, vbf, qkf, yf,
                                           gA, MA, eA, skip, hn_w, xmf);

    // out = xm @ w2^T + b2 + x
    {
        G5P p = {};
        p.Af = xmf; p.Bf = w2f;
        p.Cf = out; p.bias = b2; p.add = x;
        p.K = Cq; p.lda = 2048; p.ldb = 2048; p.ldc = 1024; p.ldadd = 1024;
        p.epi = 1|4; p.ntaps = 1; p.splitNmax = 0; p.cfMin = 0;
        hgemm<1><<<dim3(8, 48, 1), 512, 82944>>>(p);
    }
}